// round 5
// baseline (speedup 1.0000x reference)
#include <cuda_runtime.h>
#include <mma.h>
#include <math.h>

using namespace nvcuda;

#define BB 8
#define CC 128
#define HH 128
#define WW 128
#define NHH 4
#define HDD 32
#define SG2 256
#define HWP (HH*WW)      // 16384
#define NPIX (BB*HWP)    // 131072
#define KK2 25
#define SCALE 0.17677669529663687f   // 1/sqrt(32)

// ---- scratch (static device arrays; no runtime allocation) ----
static __device__ float g_q[(size_t)NPIX*CC];    // [(b*NH+h)*HW + ij]*HD + d
static __device__ float g_k[(size_t)NPIX*CC];
static __device__ float g_v[(size_t)NPIX*CC];
static __device__ float g_pwd[(size_t)NPIX*KK2]; // [p*25 + k]
static __device__ float g_agg[(size_t)NPIX*CC];  // [p*128 + c] (tf32-prerounded)
static __device__ float g_wt[128*384];           // tf32 [k][n] n: q|k|v
static __device__ float g_wpt[128*128];          // tf32 [k][n]

__device__ __forceinline__ float tf32r(float f) {
    unsigned r;
    asm("cvt.rna.tf32.f32 %0, %1;" : "=r"(r) : "f"(f));
    return __uint_as_float(r);
}
__device__ __forceinline__ float4 tf32r4(float4 v) {
    return make_float4(tf32r(v.x), tf32r(v.y), tf32r(v.z), tf32r(v.w));
}

// ============================================================
// Kernel 0: pre-round weights to tf32 (runs once per launch, ~5us)
// ============================================================
__global__ void k_prep(const float* __restrict__ w_qk, const float* __restrict__ w_v,
                       const float* __restrict__ w_proj)
{
    int i = blockIdx.x * 256 + threadIdx.x;          // 65536 threads
    if (i < 128*384) {
        int k = i / 384, n = i % 384;
        float v = (n < 256) ? w_qk[k*256 + n] : w_v[k*128 + (n - 256)];
        g_wt[i] = tf32r(v);
    } else {
        int j = i - 128*384;
        g_wpt[j] = tf32r(w_proj[j]);
    }
}

// ============================================================
// Kernel 1: QKV GEMM via WMMA tf32.
// A: x tile staged+rounded to smem ONCE (col_major m=pixel, k=chan, ld 132).
// B: direct from g_wt global (row_major [k][384], pre-rounded, L1-resident).
// All 3 bias tiles staged up front -> no syncs between N-passes.
// ============================================================
#define QKV_SMEM ((3*16*132 + 128*132)*4)   // 92928 B -> 2 blocks/SM

__global__ void __launch_bounds__(256, 2)
k_qkv_wmma(const float* __restrict__ x, const float* __restrict__ b_qk,
           const float* __restrict__ b_v)
{
    extern __shared__ float sm[];
    float* bias_s = sm;                 // [3][16][132]
    float* As     = sm + 3*16*132;      // [k=128][m=128] ld 132

    const int tid = threadIdx.x;
    const int wid = tid >> 5;
    const int wm  = wid & 3;        // m quarter (32 pixels)
    const int wn  = wid >> 2;       // n half    (64 outputs)
    const int p0  = blockIdx.x * 128;
    const int b   = p0 / HWP;
    const int ij0 = p0 % HWP;
    const float* xb = x + (size_t)b*CC*HWP + ij0;

#pragma unroll
    for (int it = 0; it < 16; it++) {
        int idx = tid + it*256;            // 4096 float4
        int k = idx >> 5, m4 = idx & 31;
        *(float4*)(As + k*132 + m4*4) =
            tf32r4(*(const float4*)(xb + (size_t)k*HWP + m4*4));
    }
    if (tid < 128) {
#pragma unroll
        for (int nt = 0; nt < 3; nt++) {
            float bv = (nt < 2) ? b_qk[nt*128 + tid] : b_v[tid];
#pragma unroll
            for (int r = 0; r < 16; r++) bias_s[(nt*16 + r)*132 + tid] = bv;
        }
    }
    __syncthreads();

#pragma unroll
    for (int nt = 0; nt < 3; nt++) {
        wmma::fragment<wmma::accumulator, 16,16,8, float> acc[2][4];
#pragma unroll
        for (int mi = 0; mi < 2; mi++)
#pragma unroll
            for (int ni = 0; ni < 4; ni++)
                wmma::load_matrix_sync(acc[mi][ni],
                    bias_s + nt*16*132 + wn*64 + ni*16, 132, wmma::mem_row_major);

        const float* Bg = g_wt + nt*128 + wn*64;
#pragma unroll
        for (int k0 = 0; k0 < CC; k0 += 8) {
            wmma::fragment<wmma::matrix_a, 16,16,8, wmma::precision::tf32,
                           wmma::col_major> a[2];
#pragma unroll
            for (int mi = 0; mi < 2; mi++)
                wmma::load_matrix_sync(a[mi], As + k0*132 + wm*32 + mi*16, 132);
            wmma::fragment<wmma::matrix_b, 16,16,8, wmma::precision::tf32,
                           wmma::row_major> bf[4];
#pragma unroll
            for (int ni = 0; ni < 4; ni++)
                wmma::load_matrix_sync(bf[ni], Bg + k0*384 + ni*16, 384);
#pragma unroll
            for (int mi = 0; mi < 2; mi++)
#pragma unroll
                for (int ni = 0; ni < 4; ni++)
                    wmma::mma_sync(acc[mi][ni], a[mi], bf[ni], acc[mi][ni]);
        }

        float* dstbase = (nt == 0) ? g_q : (nt == 1) ? g_k : g_v;
#pragma unroll
        for (int mi = 0; mi < 2; mi++)
#pragma unroll
            for (int ni = 0; ni < 4; ni++) {
                int n0 = wn*64 + ni*16;
                int head = n0 >> 5, d0 = n0 & 31;
                float* dst = dstbase +
                    ((size_t)(b*NHH + head)*HWP + ij0 + wm*32 + mi*16)*HDD + d0;
                wmma::store_matrix_sync(dst, acc[mi][ni], HDD, wmma::mem_row_major);
            }
    }
}

// ============================================================
// Kernel 2: pwd[p, k] = sum_s sims[p,s] * sims[p+off_k, s]
// ============================================================
__global__ void __launch_bounds__(256)
k_pwd(const float* __restrict__ sims)
{
    extern __shared__ float Ss[];  // [432 halo pixels][36]
    const int b  = blockIdx.z;
    const int i0 = blockIdx.y * 8;
    const int j0 = blockIdx.x * 32;
    const int tx = threadIdx.x, ty = threadIdx.y;
    const int tid = ty*32 + tx;
    const float* sb = sims + (size_t)b*HWP*SG2;

    float acc[KK2];
#pragma unroll
    for (int k=0;k<KK2;k++) acc[k] = 0.f;

    for (int scc = 0; scc < SG2; scc += 32) {
        __syncthreads();
        for (int idx = tid; idx < 432*8; idx += 256) {
            int pix = idx >> 3, v = idx & 7;
            int hr = pix / 36, hc = pix - hr*36;
            int gi = i0 - 2 + hr, gj = j0 - 2 + hc;
            float4 val = make_float4(0.f,0.f,0.f,0.f);
            if ((unsigned)gi < HH && (unsigned)gj < WW)
                val = *(const float4*)(sb + ((size_t)gi*WW + gj)*SG2 + scc + v*4);
            *(float4*)(Ss + pix*36 + v*4) = val;
        }
        __syncthreads();

        float own[32];
        const float* op = Ss + ((ty+2)*36 + (tx+2))*36;
#pragma unroll
        for (int v=0; v<8; v++) {
            float4 t = *(const float4*)(op + v*4);
            own[v*4]=t.x; own[v*4+1]=t.y; own[v*4+2]=t.z; own[v*4+3]=t.w;
        }
#pragma unroll
        for (int di=0; di<5; di++) {
#pragma unroll
            for (int dj=0; dj<5; dj++) {
                const float* np = Ss + ((ty+di)*36 + (tx+dj))*36;
                float s = 0.f;
#pragma unroll
                for (int v=0; v<8; v++) {
                    float4 t = *(const float4*)(np + v*4);
                    s = fmaf(own[v*4],   t.x, s);
                    s = fmaf(own[v*4+1], t.y, s);
                    s = fmaf(own[v*4+2], t.z, s);
                    s = fmaf(own[v*4+3], t.w, s);
                }
                acc[di*5+dj] += s;
            }
        }
    }
    const size_t p = (size_t)b*HWP + (size_t)(i0+ty)*WW + (j0+tx);
#pragma unroll
    for (int k=0;k<KK2;k++) g_pwd[p*KK2 + k] = acc[k];
}

// ============================================================
// Kernel 3: scores -> exp -> *pwd -> renorm -> V aggregation.
// Stores g_agg tf32-prerounded so k_proj needs no cvt.
// ============================================================
__global__ void __launch_bounds__(256)
k_attn()
{
    extern __shared__ float Ts[];  // [432][36]
    const int bh = blockIdx.z;
    const int b  = bh >> 2;
    const int h  = bh & 3;
    const int i0 = blockIdx.y * 8;
    const int j0 = blockIdx.x * 32;
    const int tx = threadIdx.x, ty = threadIdx.y;
    const int tid = ty*32 + tx;
    const size_t headoff = (size_t)bh*HWP*HDD;
    const int ij = (i0+ty)*WW + (j0+tx);

    float q[32];
    {
        const float* qp = g_q + headoff + (size_t)ij*HDD;
#pragma unroll
        for (int v=0; v<8; v++) {
            float4 t = *(const float4*)(qp + v*4);
            q[v*4]=t.x; q[v*4+1]=t.y; q[v*4+2]=t.z; q[v*4+3]=t.w;
        }
    }

    const float* kb = g_k + headoff;
    for (int idx = tid; idx < 432*8; idx += 256) {
        int pix = idx >> 3, v = idx & 7;
        int hr = pix / 36, hc = pix - hr*36;
        int gi = i0 - 2 + hr, gj = j0 - 2 + hc;
        float4 val = make_float4(0.f,0.f,0.f,0.f);
        if ((unsigned)gi < HH && (unsigned)gj < WW)
            val = *(const float4*)(kb + (size_t)(gi*WW + gj)*HDD + v*4);
        *(float4*)(Ts + pix*36 + v*4) = val;
    }
    __syncthreads();

    float sc[KK2];
#pragma unroll
    for (int di=0; di<5; di++) {
#pragma unroll
        for (int dj=0; dj<5; dj++) {
            const float* np = Ts + ((ty+di)*36 + (tx+dj))*36;
            float s = 0.f;
#pragma unroll
            for (int v=0; v<8; v++) {
                float4 t = *(const float4*)(np + v*4);
                s = fmaf(q[v*4],   t.x, s);
                s = fmaf(q[v*4+1], t.y, s);
                s = fmaf(q[v*4+2], t.z, s);
                s = fmaf(q[v*4+3], t.w, s);
            }
            sc[di*5+dj] = s * SCALE;
        }
    }
    __syncthreads();

    const float* vb = g_v + headoff;
    for (int idx = tid; idx < 432*8; idx += 256) {
        int pix = idx >> 3, v = idx & 7;
        int hr = pix / 36, hc = pix - hr*36;
        int gi = i0 - 2 + hr, gj = j0 - 2 + hc;
        float4 val = make_float4(0.f,0.f,0.f,0.f);
        if ((unsigned)gi < HH && (unsigned)gj < WW)
            val = *(const float4*)(vb + (size_t)(gi*WW + gj)*HDD + v*4);
        *(float4*)(Ts + pix*36 + v*4) = val;
    }

    float m = sc[0];
#pragma unroll
    for (int k=1;k<KK2;k++) m = fmaxf(m, sc[k]);
    const float* pw = g_pwd + ((size_t)b*HWP + ij)*KK2;
    float w[KK2]; float ssum = 0.f;
#pragma unroll
    for (int k=0;k<KK2;k++) { w[k] = __expf(sc[k]-m) * pw[k]; ssum += w[k]; }
    const float inv = 1.f / fmaxf(ssum, 1e-30f);

    __syncthreads();

    float out[32];
#pragma unroll
    for (int v=0;v<32;v++) out[v] = 0.f;
#pragma unroll
    for (int di=0; di<5; di++) {
#pragma unroll
        for (int dj=0; dj<5; dj++) {
            float wk = w[di*5+dj] * inv;
            const float* np = Ts + ((ty+di)*36 + (tx+dj))*36;
#pragma unroll
            for (int v=0; v<8; v++) {
                float4 t = *(const float4*)(np + v*4);
                out[v*4]   = fmaf(wk, t.x, out[v*4]);
                out[v*4+1] = fmaf(wk, t.y, out[v*4+1]);
                out[v*4+2] = fmaf(wk, t.z, out[v*4+2]);
                out[v*4+3] = fmaf(wk, t.w, out[v*4+3]);
            }
        }
    }
    float* ag = g_agg + ((size_t)b*HWP + ij)*CC + h*HDD;
#pragma unroll
    for (int v=0; v<8; v++)
        *(float4*)(ag + v*4) = make_float4(tf32r(out[v*4]),   tf32r(out[v*4+1]),
                                           tf32r(out[v*4+2]), tf32r(out[v*4+3]));
}

// ============================================================
// Kernel 4: proj GEMM via WMMA tf32 + free BCHW transpose store.
// A: g_agg (pre-rounded) staged to smem, plain copies.
// B: direct from g_wpt global (pre-rounded).
// ============================================================
#define PRJ_SMEM ((16*132 + 128*132)*4)     // 76032 B -> 2 blocks/SM

__global__ void __launch_bounds__(256, 2)
k_proj_wmma(const float* __restrict__ b_proj, float* __restrict__ out)
{
    extern __shared__ float sm[];
    float* bias_s = sm;                 // [16][132]
    float* As     = sm + 16*132;        // [m=128][k=128] ld 132 (row_major)

    const int tid = threadIdx.x;
    const int wid = tid >> 5;
    const int wm  = wid & 3;
    const int wn  = wid >> 2;
    const int p0  = blockIdx.x * 128;
    const int b   = p0 / HWP;
    const int ij0 = p0 % HWP;

    const float* ab = g_agg + (size_t)p0 * CC;
#pragma unroll
    for (int it = 0; it < 16; it++) {
        int idx = tid + it*256;
        int m = idx >> 5, k4 = idx & 31;
        *(float4*)(As + m*132 + k4*4) = *(const float4*)(ab + (size_t)m*CC + k4*4);
    }
    if (tid < 128) {
        float bv = b_proj[tid];
#pragma unroll
        for (int r = 0; r < 16; r++) bias_s[r*132 + tid] = bv;
    }
    __syncthreads();

    wmma::fragment<wmma::accumulator, 16,16,8, float> acc[2][4];
#pragma unroll
    for (int mi = 0; mi < 2; mi++)
#pragma unroll
        for (int ni = 0; ni < 4; ni++)
            wmma::load_matrix_sync(acc[mi][ni], bias_s + wn*64 + ni*16,
                                   132, wmma::mem_row_major);

    const float* Bg = g_wpt + wn*64;
#pragma unroll
    for (int k0 = 0; k0 < CC; k0 += 8) {
        wmma::fragment<wmma::matrix_a, 16,16,8, wmma::precision::tf32,
                       wmma::row_major> a[2];
#pragma unroll
        for (int mi = 0; mi < 2; mi++)
            wmma::load_matrix_sync(a[mi], As + (wm*32 + mi*16)*132 + k0, 132);
        wmma::fragment<wmma::matrix_b, 16,16,8, wmma::precision::tf32,
                       wmma::row_major> bf[4];
#pragma unroll
        for (int ni = 0; ni < 4; ni++)
            wmma::load_matrix_sync(bf[ni], Bg + k0*128 + ni*16, 128);
#pragma unroll
        for (int mi = 0; mi < 2; mi++)
#pragma unroll
            for (int ni = 0; ni < 4; ni++)
                wmma::mma_sync(acc[mi][ni], a[mi], bf[ni], acc[mi][ni]);
    }

    float* ob = out + (size_t)b*CC*HWP + ij0;
#pragma unroll
    for (int mi = 0; mi < 2; mi++)
#pragma unroll
        for (int ni = 0; ni < 4; ni++) {
            int n0 = wn*64 + ni*16;
            int m0 = wm*32 + mi*16;
            wmma::store_matrix_sync(ob + (size_t)n0*HWP + m0, acc[mi][ni],
                                    HWP, wmma::mem_col_major);
        }
}

// ============================================================
extern "C" void kernel_launch(void* const* d_in, const int* in_sizes, int n_in,
                              void* d_out, int out_size)
{
    const float* x      = (const float*)d_in[0];
    const float* sims   = (const float*)d_in[1];
    const float* w_qk   = (const float*)d_in[2];
    const float* b_qk   = (const float*)d_in[3];
    const float* w_v    = (const float*)d_in[4];
    const float* b_v    = (const float*)d_in[5];
    const float* w_proj = (const float*)d_in[6];
    const float* b_proj = (const float*)d_in[7];
    float* out = (float*)d_out;

    cudaFuncSetAttribute(k_qkv_wmma,  cudaFuncAttributeMaxDynamicSharedMemorySize, QKV_SMEM);
    cudaFuncSetAttribute(k_pwd,       cudaFuncAttributeMaxDynamicSharedMemorySize, 432*36*4);
    cudaFuncSetAttribute(k_attn,      cudaFuncAttributeMaxDynamicSharedMemorySize, 432*36*4);
    cudaFuncSetAttribute(k_proj_wmma, cudaFuncAttributeMaxDynamicSharedMemorySize, PRJ_SMEM);

    k_prep     <<<256, 256>>>(w_qk, w_v, w_proj);
    k_qkv_wmma <<<NPIX/128, 256, QKV_SMEM>>>(x, b_qk, b_v);
    k_pwd      <<<dim3(WW/32, HH/8, BB),     dim3(32,8), 432*36*4>>>(sims);
    k_attn     <<<dim3(WW/32, HH/8, BB*NHH), dim3(32,8), 432*36*4>>>();
    k_proj_wmma<<<NPIX/128, 256, PRJ_SMEM>>>(b_proj, out);
}

// round 6
// speedup vs baseline: 1.3111x; 1.3111x over previous
#include <cuda_runtime.h>
#include <mma.h>
#include <cuda_fp16.h>
#include <math.h>

using namespace nvcuda;

#define BB 8
#define CC 128
#define HH 128
#define WW 128
#define NHH 4
#define HDD 32
#define SG2 256
#define HWP (HH*WW)      // 16384
#define NPIX (BB*HWP)    // 131072
#define KK2 25
#define SCALE 0.17677669529663687f   // 1/sqrt(32)

// ---- scratch (static device arrays; no runtime allocation) ----
static __device__ float g_q[(size_t)NPIX*CC];    // [(b*NH+h)*HW + ij]*HD + d
static __device__ float g_k[(size_t)NPIX*CC];
static __device__ float g_v[(size_t)NPIX*CC];
static __device__ float g_pwd[(size_t)NPIX*KK2]; // [p*25 + k]
static __device__ float g_agg[(size_t)NPIX*CC];  // [p*128 + c]

#define GEMM_SMEM ((16*132 + 128*132)*4)

// ============================================================
// Kernel 1: QKV GEMM via WMMA tf32 (R3-proven config).
// A: directly from global x (col_major m=pixel, k=chan, ld=HWP).
// B: staged in smem row_major [k][n] per N-pass. Bias in acc init.
// ============================================================
__global__ void __launch_bounds__(256, 2)
k_qkv_wmma(const float* __restrict__ x, const float* __restrict__ w_qk,
           const float* __restrict__ b_qk, const float* __restrict__ w_v,
           const float* __restrict__ b_v)
{
    extern __shared__ float sm[];
    float* bias_s = sm;             // [16][132]
    float* Bs     = sm + 16*132;    // [128][132]

    const int tid = threadIdx.x;
    const int wid = tid >> 5;
    const int wm  = wid & 3;        // m quarter  (32 pixels)
    const int wn  = wid >> 2;       // n half     (64 outputs)
    const int p0  = blockIdx.x * 128;
    const int b   = p0 / HWP;
    const int ij0 = p0 % HWP;
    const float* xb = x + (size_t)b*CC*HWP + ij0;

    for (int nt = 0; nt < 3; nt++) {
        __syncthreads();
#pragma unroll
        for (int it = 0; it < 16; it++) {
            int idx = tid + it*256;            // 4096 float4
            int k = idx >> 5, n4 = idx & 31;
            const float* src = (nt < 2) ? (w_qk + k*2*CC + nt*128 + n4*4)
                                        : (w_v  + k*CC  + n4*4);
            *(float4*)(Bs + k*132 + n4*4) = *(const float4*)src;
        }
        if (tid < 128) {
            float bv = (nt < 2) ? b_qk[nt*128 + tid] : b_v[tid];
#pragma unroll
            for (int r = 0; r < 16; r++) bias_s[r*132 + tid] = bv;
        }
        __syncthreads();

        wmma::fragment<wmma::accumulator, 16,16,8, float> acc[2][4];
#pragma unroll
        for (int mi = 0; mi < 2; mi++)
#pragma unroll
            for (int ni = 0; ni < 4; ni++)
                wmma::load_matrix_sync(acc[mi][ni], bias_s + wn*64 + ni*16,
                                       132, wmma::mem_row_major);

#pragma unroll
        for (int k0 = 0; k0 < CC; k0 += 8) {
            wmma::fragment<wmma::matrix_a, 16,16,8, wmma::precision::tf32,
                           wmma::col_major> a[2];
#pragma unroll
            for (int mi = 0; mi < 2; mi++) {
                wmma::load_matrix_sync(a[mi],
                    xb + (size_t)k0*HWP + (wm*32 + mi*16), HWP);
#pragma unroll
                for (int e = 0; e < a[mi].num_elements; e++)
                    a[mi].x[e] = wmma::__float_to_tf32(a[mi].x[e]);
            }
            wmma::fragment<wmma::matrix_b, 16,16,8, wmma::precision::tf32,
                           wmma::row_major> bf[4];
#pragma unroll
            for (int ni = 0; ni < 4; ni++) {
                wmma::load_matrix_sync(bf[ni], Bs + k0*132 + wn*64 + ni*16, 132);
#pragma unroll
                for (int e = 0; e < bf[ni].num_elements; e++)
                    bf[ni].x[e] = wmma::__float_to_tf32(bf[ni].x[e]);
            }
#pragma unroll
            for (int mi = 0; mi < 2; mi++)
#pragma unroll
                for (int ni = 0; ni < 4; ni++)
                    wmma::mma_sync(acc[mi][ni], a[mi], bf[ni], acc[mi][ni]);
        }

        float* dstbase = (nt == 0) ? g_q : (nt == 1) ? g_k : g_v;
#pragma unroll
        for (int mi = 0; mi < 2; mi++)
#pragma unroll
            for (int ni = 0; ni < 4; ni++) {
                int n0 = wn*64 + ni*16;
                int head = n0 >> 5, d0 = n0 & 31;
                float* dst = dstbase +
                    ((size_t)(b*NHH + head)*HWP + ij0 + wm*32 + mi*16)*HDD + d0;
                wmma::store_matrix_sync(dst, acc[mi][ni], HDD, wmma::mem_row_major);
            }
    }
}

// ============================================================
// Kernel 2: pwd[p, k] = sum_s sims[p,s] * sims[p+off_k, s]
// ============================================================
__global__ void __launch_bounds__(256)
k_pwd(const float* __restrict__ sims)
{
    extern __shared__ float Ss[];  // [432 halo pixels][36]
    const int b  = blockIdx.z;
    const int i0 = blockIdx.y * 8;
    const int j0 = blockIdx.x * 32;
    const int tx = threadIdx.x, ty = threadIdx.y;
    const int tid = ty*32 + tx;
    const float* sb = sims + (size_t)b*HWP*SG2;

    float acc[KK2];
#pragma unroll
    for (int k=0;k<KK2;k++) acc[k] = 0.f;

    for (int scc = 0; scc < SG2; scc += 32) {
        __syncthreads();
        for (int idx = tid; idx < 432*8; idx += 256) {
            int pix = idx >> 3, v = idx & 7;
            int hr = pix / 36, hc = pix - hr*36;
            int gi = i0 - 2 + hr, gj = j0 - 2 + hc;
            float4 val = make_float4(0.f,0.f,0.f,0.f);
            if ((unsigned)gi < HH && (unsigned)gj < WW)
                val = *(const float4*)(sb + ((size_t)gi*WW + gj)*SG2 + scc + v*4);
            *(float4*)(Ss + pix*36 + v*4) = val;
        }
        __syncthreads();

        float own[32];
        const float* op = Ss + ((ty+2)*36 + (tx+2))*36;
#pragma unroll
        for (int v=0; v<8; v++) {
            float4 t = *(const float4*)(op + v*4);
            own[v*4]=t.x; own[v*4+1]=t.y; own[v*4+2]=t.z; own[v*4+3]=t.w;
        }
#pragma unroll
        for (int di=0; di<5; di++) {
#pragma unroll
            for (int dj=0; dj<5; dj++) {
                const float* np = Ss + ((ty+di)*36 + (tx+dj))*36;
                float s = 0.f;
#pragma unroll
                for (int v=0; v<8; v++) {
                    float4 t = *(const float4*)(np + v*4);
                    s = fmaf(own[v*4],   t.x, s);
                    s = fmaf(own[v*4+1], t.y, s);
                    s = fmaf(own[v*4+2], t.z, s);
                    s = fmaf(own[v*4+3], t.w, s);
                }
                acc[di*5+dj] += s;
            }
        }
    }
    const size_t p = (size_t)b*HWP + (size_t)(i0+ty)*WW + (j0+tx);
#pragma unroll
    for (int k=0;k<KK2;k++) g_pwd[p*KK2 + k] = acc[k];
}

// ============================================================
// Kernel 3: attention + V aggregation, fp16 K/V halos in smem.
// exp needs no max-subtraction (denominator cancels vs pwd renorm).
// K and V staged together -> single __syncthreads.
// Row stride 40 halfs (80 B): LDS.128 phase groups (t*5)%8 -> conflict-free.
// ============================================================
#define ATT_SMEM (2*432*40*2)   // Kh + Vh, 69120 B -> 2 blocks/SM

__global__ void __launch_bounds__(256, 2)
k_attn()
{
    extern __shared__ __half sh[];
    __half* Kh = sh;              // [432][40]
    __half* Vh = sh + 432*40;

    const int bh = blockIdx.z;
    const int b  = bh >> 2;
    const int h  = bh & 3;
    const int i0 = blockIdx.y * 8;
    const int j0 = blockIdx.x * 32;
    const int tx = threadIdx.x, ty = threadIdx.y;
    const int tid = ty*32 + tx;
    const size_t headoff = (size_t)bh*HWP*HDD;
    const int ij = (i0+ty)*WW + (j0+tx);

    // ---- stage K and V halos as fp16 (one pass, overlapped loads) ----
    const float* kb = g_k + headoff;
    const float* vb = g_v + headoff;
    for (int idx = tid; idx < 432*4; idx += 256) {
        int pix = idx >> 2, v = idx & 3;
        int hr = pix / 36, hc = pix - hr*36;
        int gi = i0 - 2 + hr, gj = j0 - 2 + hc;
        uint4 kp = make_uint4(0,0,0,0), vp = make_uint4(0,0,0,0);
        if ((unsigned)gi < HH && (unsigned)gj < WW) {
            const float* ks = kb + (size_t)(gi*WW + gj)*HDD + v*8;
            const float* vs = vb + (size_t)(gi*WW + gj)*HDD + v*8;
            float4 ka = *(const float4*)ks, kc = *(const float4*)(ks+4);
            float4 va = *(const float4*)vs, vc = *(const float4*)(vs+4);
            __half2 t;
            t = __floats2half2_rn(ka.x, ka.y); kp.x = *(unsigned*)&t;
            t = __floats2half2_rn(ka.z, ka.w); kp.y = *(unsigned*)&t;
            t = __floats2half2_rn(kc.x, kc.y); kp.z = *(unsigned*)&t;
            t = __floats2half2_rn(kc.z, kc.w); kp.w = *(unsigned*)&t;
            t = __floats2half2_rn(va.x, va.y); vp.x = *(unsigned*)&t;
            t = __floats2half2_rn(va.z, va.w); vp.y = *(unsigned*)&t;
            t = __floats2half2_rn(vc.x, vc.y); vp.z = *(unsigned*)&t;
            t = __floats2half2_rn(vc.z, vc.w); vp.w = *(unsigned*)&t;
        }
        *(uint4*)(Kh + pix*40 + v*8) = kp;
        *(uint4*)(Vh + pix*40 + v*8) = vp;
    }

    // q for this pixel (fp32)
    float q[32];
    {
        const float* qp = g_q + headoff + (size_t)ij*HDD;
#pragma unroll
        for (int v=0; v<8; v++) {
            float4 t = *(const float4*)(qp + v*4);
            q[v*4]=t.x; q[v*4+1]=t.y; q[v*4+2]=t.z; q[v*4+3]=t.w;
        }
    }
    __syncthreads();

    // ---- scores -> weights (no max needed) ----
    const float* pw = g_pwd + ((size_t)b*HWP + ij)*KK2;
    float w[KK2]; float ssum = 0.f;
#pragma unroll
    for (int di=0; di<5; di++) {
#pragma unroll
        for (int dj=0; dj<5; dj++) {
            const __half* np = Kh + ((ty+di)*36 + (tx+dj))*40;
            float s = 0.f;
#pragma unroll
            for (int v=0; v<4; v++) {
                uint4 r = *(const uint4*)(np + v*8);
                float2 f0 = __half22float2(*(__half2*)&r.x);
                float2 f1 = __half22float2(*(__half2*)&r.y);
                float2 f2 = __half22float2(*(__half2*)&r.z);
                float2 f3 = __half22float2(*(__half2*)&r.w);
                s = fmaf(q[v*8+0], f0.x, s);
                s = fmaf(q[v*8+1], f0.y, s);
                s = fmaf(q[v*8+2], f1.x, s);
                s = fmaf(q[v*8+3], f1.y, s);
                s = fmaf(q[v*8+4], f2.x, s);
                s = fmaf(q[v*8+5], f2.y, s);
                s = fmaf(q[v*8+6], f3.x, s);
                s = fmaf(q[v*8+7], f3.y, s);
            }
            int kk = di*5+dj;
            w[kk] = __expf(s * SCALE) * pw[kk];
            ssum += w[kk];
        }
    }
    const float inv = 1.f / fmaxf(ssum, 1e-30f);

    // ---- V aggregation ----
    float out[32];
#pragma unroll
    for (int v=0;v<32;v++) out[v] = 0.f;
#pragma unroll
    for (int di=0; di<5; di++) {
#pragma unroll
        for (int dj=0; dj<5; dj++) {
            float wk = w[di*5+dj] * inv;
            const __half* np = Vh + ((ty+di)*36 + (tx+dj))*40;
#pragma unroll
            for (int v=0; v<4; v++) {
                uint4 r = *(const uint4*)(np + v*8);
                float2 f0 = __half22float2(*(__half2*)&r.x);
                float2 f1 = __half22float2(*(__half2*)&r.y);
                float2 f2 = __half22float2(*(__half2*)&r.z);
                float2 f3 = __half22float2(*(__half2*)&r.w);
                out[v*8+0] = fmaf(wk, f0.x, out[v*8+0]);
                out[v*8+1] = fmaf(wk, f0.y, out[v*8+1]);
                out[v*8+2] = fmaf(wk, f1.x, out[v*8+2]);
                out[v*8+3] = fmaf(wk, f1.y, out[v*8+3]);
                out[v*8+4] = fmaf(wk, f2.x, out[v*8+4]);
                out[v*8+5] = fmaf(wk, f2.y, out[v*8+5]);
                out[v*8+6] = fmaf(wk, f3.x, out[v*8+6]);
                out[v*8+7] = fmaf(wk, f3.y, out[v*8+7]);
            }
        }
    }
    float* ag = g_agg + ((size_t)b*HWP + ij)*CC + h*HDD;
#pragma unroll
    for (int v=0; v<8; v++)
        *(float4*)(ag + v*4) = make_float4(out[v*4], out[v*4+1],
                                           out[v*4+2], out[v*4+3]);
}

// ============================================================
// Kernel 4: proj GEMM via WMMA tf32 + free BCHW transpose (R3-proven).
// A: g_agg row_major ld=128 direct from global; B staged in smem.
// ============================================================
__global__ void __launch_bounds__(256, 2)
k_proj_wmma(const float* __restrict__ w_proj, const float* __restrict__ b_proj,
            float* __restrict__ out)
{
    extern __shared__ float sm[];
    float* bias_s = sm;             // [16][132]
    float* Bs     = sm + 16*132;    // [128][132]

    const int tid = threadIdx.x;
    const int wid = tid >> 5;
    const int wm  = wid & 3;
    const int wn  = wid >> 2;
    const int p0  = blockIdx.x * 128;
    const int b   = p0 / HWP;
    const int ij0 = p0 % HWP;

#pragma unroll
    for (int it = 0; it < 16; it++) {
        int idx = tid + it*256;
        int k = idx >> 5, n4 = idx & 31;
        *(float4*)(Bs + k*132 + n4*4) = *(const float4*)(w_proj + k*CC + n4*4);
    }
    if (tid < 128) {
        float bv = b_proj[tid];
#pragma unroll
        for (int r = 0; r < 16; r++) bias_s[r*132 + tid] = bv;
    }
    __syncthreads();

    wmma::fragment<wmma::accumulator, 16,16,8, float> acc[2][4];
#pragma unroll
    for (int mi = 0; mi < 2; mi++)
#pragma unroll
        for (int ni = 0; ni < 4; ni++)
            wmma::load_matrix_sync(acc[mi][ni], bias_s + wn*64 + ni*16,
                                   132, wmma::mem_row_major);

    const float* ab = g_agg + (size_t)p0 * CC;
#pragma unroll
    for (int k0 = 0; k0 < CC; k0 += 8) {
        wmma::fragment<wmma::matrix_a, 16,16,8, wmma::precision::tf32,
                       wmma::row_major> a[2];
#pragma unroll
        for (int mi = 0; mi < 2; mi++) {
            wmma::load_matrix_sync(a[mi], ab + (size_t)(wm*32 + mi*16)*CC + k0, CC);
#pragma unroll
            for (int e = 0; e < a[mi].num_elements; e++)
                a[mi].x[e] = wmma::__float_to_tf32(a[mi].x[e]);
        }
        wmma::fragment<wmma::matrix_b, 16,16,8, wmma::precision::tf32,
                       wmma::row_major> bf[4];
#pragma unroll
        for (int ni = 0; ni < 4; ni++) {
            wmma::load_matrix_sync(bf[ni], Bs + k0*132 + wn*64 + ni*16, 132);
#pragma unroll
            for (int e = 0; e < bf[ni].num_elements; e++)
                bf[ni].x[e] = wmma::__float_to_tf32(bf[ni].x[e]);
        }
#pragma unroll
        for (int mi = 0; mi < 2; mi++)
#pragma unroll
            for (int ni = 0; ni < 4; ni++)
                wmma::mma_sync(acc[mi][ni], a[mi], bf[ni], acc[mi][ni]);
    }

    float* ob = out + (size_t)b*CC*HWP + ij0;
#pragma unroll
    for (int mi = 0; mi < 2; mi++)
#pragma unroll
        for (int ni = 0; ni < 4; ni++) {
            int n0 = wn*64 + ni*16;
            int m0 = wm*32 + mi*16;
            wmma::store_matrix_sync(ob + (size_t)n0*HWP + m0, acc[mi][ni],
                                    HWP, wmma::mem_col_major);
        }
}

// ============================================================
extern "C" void kernel_launch(void* const* d_in, const int* in_sizes, int n_in,
                              void* d_out, int out_size)
{
    const float* x      = (const float*)d_in[0];
    const float* sims   = (const float*)d_in[1];
    const float* w_qk   = (const float*)d_in[2];
    const float* b_qk   = (const float*)d_in[3];
    const float* w_v    = (const float*)d_in[4];
    const float* b_v    = (const float*)d_in[5];
    const float* w_proj = (const float*)d_in[6];
    const float* b_proj = (const float*)d_in[7];
    float* out = (float*)d_out;

    cudaFuncSetAttribute(k_qkv_wmma,  cudaFuncAttributeMaxDynamicSharedMemorySize, GEMM_SMEM);
    cudaFuncSetAttribute(k_pwd,       cudaFuncAttributeMaxDynamicSharedMemorySize, 432*36*4);
    cudaFuncSetAttribute(k_attn,      cudaFuncAttributeMaxDynamicSharedMemorySize, ATT_SMEM);
    cudaFuncSetAttribute(k_proj_wmma, cudaFuncAttributeMaxDynamicSharedMemorySize, GEMM_SMEM);

    k_qkv_wmma <<<NPIX/128, 256, GEMM_SMEM>>>(x, w_qk, b_qk, w_v, b_v);
    k_pwd      <<<dim3(WW/32, HH/8, BB),     dim3(32,8), 432*36*4>>>(sims);
    k_attn     <<<dim3(WW/32, HH/8, BB*NHH), dim3(32,8), ATT_SMEM>>>();
    k_proj_wmma<<<NPIX/128, 256, GEMM_SMEM>>>(w_proj, b_proj, out);
}

// round 7
// speedup vs baseline: 1.8917x; 1.4428x over previous
#include <cuda_runtime.h>
#include <mma.h>
#include <cuda_fp16.h>
#include <math.h>

using namespace nvcuda;

#define BB 8
#define CC 128
#define HH 128
#define WW 128
#define NHH 4
#define HDD 32
#define SG2 256
#define HWP (HH*WW)      // 16384
#define NPIX (BB*HWP)    // 131072
#define KK2 25
#define SCALE 0.17677669529663687f   // 1/sqrt(32)

// ---- scratch (static device arrays; no runtime allocation) ----
static __device__ float g_q[(size_t)NPIX*CC];    // [(b*NH+h)*HW + ij]*HD + d
static __device__ float g_k[(size_t)NPIX*CC];
static __device__ float g_v[(size_t)NPIX*CC];
static __device__ float g_pwd[(size_t)NPIX*KK2]; // [p*25 + k]
static __device__ float g_agg[(size_t)NPIX*CC];  // [p*128 + c]

#define LDH 136                       // fp16 smem row stride (halfs)
// smem: bias fp32 [16][132] | A fp16 [128][136] | B fp16 [128][136]
#define GEMM_SMEM (16*132*4 + 2*128*LDH*2)   // 78080 B -> 2 blocks/SM

__device__ __forceinline__ uint2 f4toh4(float4 v) {
    __half2 lo = __floats2half2_rn(v.x, v.y);
    __half2 hi = __floats2half2_rn(v.z, v.w);
    uint2 r;
    r.x = *(unsigned*)&lo;
    r.y = *(unsigned*)&hi;
    return r;
}

// ============================================================
// Kernel 1: QKV GEMM via WMMA fp16 (fp32 accumulate).
// A: x tile staged+converted to fp16 smem ONCE (col_major m=pix,k=chan).
// B: per-N-pass weight tile staged fp16 (row_major k,n).
// Bias folded into acc init. D stored fp32 to q/k/v [pix][d], ld=32.
// ============================================================
__global__ void __launch_bounds__(256, 2)
k_qkv_wmma(const float* __restrict__ x, const float* __restrict__ w_qk,
           const float* __restrict__ b_qk, const float* __restrict__ w_v,
           const float* __restrict__ b_v)
{
    extern __shared__ char smraw[];
    float*  bias_s = (float*)smraw;                    // [16][132]
    __half* As     = (__half*)(smraw + 16*132*4);      // [k=128][m=128] ld LDH
    __half* Bs     = As + 128*LDH;                     // [k=128][n=128] ld LDH

    const int tid = threadIdx.x;
    const int wid = tid >> 5;
    const int wm  = wid & 3;        // m quarter  (32 pixels)
    const int wn  = wid >> 2;       // n half     (64 outputs)
    const int p0  = blockIdx.x * 128;
    const int b   = p0 / HWP;
    const int ij0 = p0 % HWP;
    const float* xb = x + (size_t)b*CC*HWP + ij0;

    // stage A once: As[k*LDH + m] = fp16(x[b, k, ij0+m])
#pragma unroll
    for (int it = 0; it < 16; it++) {
        int idx = tid + it*256;            // 4096 float4
        int k = idx >> 5, m4 = idx & 31;
        *(uint2*)(As + k*LDH + m4*4) =
            f4toh4(*(const float4*)(xb + (size_t)k*HWP + m4*4));
    }

    for (int nt = 0; nt < 3; nt++) {
        __syncthreads();   // prev pass done with Bs (covers As stage at nt=0)
#pragma unroll
        for (int it = 0; it < 16; it++) {
            int idx = tid + it*256;
            int k = idx >> 5, n4 = idx & 31;
            const float* src = (nt < 2) ? (w_qk + k*2*CC + nt*128 + n4*4)
                                        : (w_v  + k*CC  + n4*4);
            *(uint2*)(Bs + k*LDH + n4*4) = f4toh4(*(const float4*)src);
        }
        if (tid < 128) {
            float bv = (nt < 2) ? b_qk[nt*128 + tid] : b_v[tid];
#pragma unroll
            for (int r = 0; r < 16; r++) bias_s[r*132 + tid] = bv;
        }
        __syncthreads();

        wmma::fragment<wmma::accumulator, 16,16,16, float> acc[2][4];
#pragma unroll
        for (int mi = 0; mi < 2; mi++)
#pragma unroll
            for (int ni = 0; ni < 4; ni++)
                wmma::load_matrix_sync(acc[mi][ni], bias_s + wn*64 + ni*16,
                                       132, wmma::mem_row_major);

#pragma unroll
        for (int k0 = 0; k0 < CC; k0 += 16) {
            wmma::fragment<wmma::matrix_a, 16,16,16, __half, wmma::col_major> a[2];
#pragma unroll
            for (int mi = 0; mi < 2; mi++)
                wmma::load_matrix_sync(a[mi], As + k0*LDH + wm*32 + mi*16, LDH);
            wmma::fragment<wmma::matrix_b, 16,16,16, __half, wmma::row_major> bf[4];
#pragma unroll
            for (int ni = 0; ni < 4; ni++)
                wmma::load_matrix_sync(bf[ni], Bs + k0*LDH + wn*64 + ni*16, LDH);
#pragma unroll
            for (int mi = 0; mi < 2; mi++)
#pragma unroll
                for (int ni = 0; ni < 4; ni++)
                    wmma::mma_sync(acc[mi][ni], a[mi], bf[ni], acc[mi][ni]);
        }

        float* dstbase = (nt == 0) ? g_q : (nt == 1) ? g_k : g_v;
#pragma unroll
        for (int mi = 0; mi < 2; mi++)
#pragma unroll
            for (int ni = 0; ni < 4; ni++) {
                int n0 = wn*64 + ni*16;
                int head = n0 >> 5, d0 = n0 & 31;
                float* dst = dstbase +
                    ((size_t)(b*NHH + head)*HWP + ij0 + wm*32 + mi*16)*HDD + d0;
                wmma::store_matrix_sync(dst, acc[mi][ni], HDD, wmma::mem_row_major);
            }
    }
}

// ============================================================
// Kernel 2: pwd[p, k] = sum_s sims[p,s] * sims[p+off_k, s]
// ============================================================
__global__ void __launch_bounds__(256)
k_pwd(const float* __restrict__ sims)
{
    extern __shared__ float Ss[];  // [432 halo pixels][36]
    const int b  = blockIdx.z;
    const int i0 = blockIdx.y * 8;
    const int j0 = blockIdx.x * 32;
    const int tx = threadIdx.x, ty = threadIdx.y;
    const int tid = ty*32 + tx;
    const float* sb = sims + (size_t)b*HWP*SG2;

    float acc[KK2];
#pragma unroll
    for (int k=0;k<KK2;k++) acc[k] = 0.f;

    for (int scc = 0; scc < SG2; scc += 32) {
        __syncthreads();
        for (int idx = tid; idx < 432*8; idx += 256) {
            int pix = idx >> 3, v = idx & 7;
            int hr = pix / 36, hc = pix - hr*36;
            int gi = i0 - 2 + hr, gj = j0 - 2 + hc;
            float4 val = make_float4(0.f,0.f,0.f,0.f);
            if ((unsigned)gi < HH && (unsigned)gj < WW)
                val = *(const float4*)(sb + ((size_t)gi*WW + gj)*SG2 + scc + v*4);
            *(float4*)(Ss + pix*36 + v*4) = val;
        }
        __syncthreads();

        float own[32];
        const float* op = Ss + ((ty+2)*36 + (tx+2))*36;
#pragma unroll
        for (int v=0; v<8; v++) {
            float4 t = *(const float4*)(op + v*4);
            own[v*4]=t.x; own[v*4+1]=t.y; own[v*4+2]=t.z; own[v*4+3]=t.w;
        }
#pragma unroll
        for (int di=0; di<5; di++) {
#pragma unroll
            for (int dj=0; dj<5; dj++) {
                const float* np = Ss + ((ty+di)*36 + (tx+dj))*36;
                float s = 0.f;
#pragma unroll
                for (int v=0; v<8; v++) {
                    float4 t = *(const float4*)(np + v*4);
                    s = fmaf(own[v*4],   t.x, s);
                    s = fmaf(own[v*4+1], t.y, s);
                    s = fmaf(own[v*4+2], t.z, s);
                    s = fmaf(own[v*4+3], t.w, s);
                }
                acc[di*5+dj] += s;
            }
        }
    }
    const size_t p = (size_t)b*HWP + (size_t)(i0+ty)*WW + (j0+tx);
#pragma unroll
    for (int k=0;k<KK2;k++) g_pwd[p*KK2 + k] = acc[k];
}

// ============================================================
// Kernel 3: attention + V aggregation, fp16 K/V halos in smem.
// exp needs no max-subtraction (denominator cancels vs pwd renorm).
// ============================================================
#define ATT_SMEM (2*432*40*2)   // Kh + Vh, 69120 B -> 2 blocks/SM

__global__ void __launch_bounds__(256, 2)
k_attn()
{
    extern __shared__ __half sh[];
    __half* Kh = sh;              // [432][40]
    __half* Vh = sh + 432*40;

    const int bh = blockIdx.z;
    const int b  = bh >> 2;
    const int h  = bh & 3;
    const int i0 = blockIdx.y * 8;
    const int j0 = blockIdx.x * 32;
    const int tx = threadIdx.x, ty = threadIdx.y;
    const int tid = ty*32 + tx;
    const size_t headoff = (size_t)bh*HWP*HDD;
    const int ij = (i0+ty)*WW + (j0+tx);

    const float* kb = g_k + headoff;
    const float* vb = g_v + headoff;
    for (int idx = tid; idx < 432*4; idx += 256) {
        int pix = idx >> 2, v = idx & 3;
        int hr = pix / 36, hc = pix - hr*36;
        int gi = i0 - 2 + hr, gj = j0 - 2 + hc;
        uint4 kp = make_uint4(0,0,0,0), vp = make_uint4(0,0,0,0);
        if ((unsigned)gi < HH && (unsigned)gj < WW) {
            const float* ks = kb + (size_t)(gi*WW + gj)*HDD + v*8;
            const float* vs = vb + (size_t)(gi*WW + gj)*HDD + v*8;
            float4 ka = *(const float4*)ks, kc = *(const float4*)(ks+4);
            float4 va = *(const float4*)vs, vc = *(const float4*)(vs+4);
            __half2 t;
            t = __floats2half2_rn(ka.x, ka.y); kp.x = *(unsigned*)&t;
            t = __floats2half2_rn(ka.z, ka.w); kp.y = *(unsigned*)&t;
            t = __floats2half2_rn(kc.x, kc.y); kp.z = *(unsigned*)&t;
            t = __floats2half2_rn(kc.z, kc.w); kp.w = *(unsigned*)&t;
            t = __floats2half2_rn(va.x, va.y); vp.x = *(unsigned*)&t;
            t = __floats2half2_rn(va.z, va.w); vp.y = *(unsigned*)&t;
            t = __floats2half2_rn(vc.x, vc.y); vp.z = *(unsigned*)&t;
            t = __floats2half2_rn(vc.z, vc.w); vp.w = *(unsigned*)&t;
        }
        *(uint4*)(Kh + pix*40 + v*8) = kp;
        *(uint4*)(Vh + pix*40 + v*8) = vp;
    }

    float q[32];
    {
        const float* qp = g_q + headoff + (size_t)ij*HDD;
#pragma unroll
        for (int v=0; v<8; v++) {
            float4 t = *(const float4*)(qp + v*4);
            q[v*4]=t.x; q[v*4+1]=t.y; q[v*4+2]=t.z; q[v*4+3]=t.w;
        }
    }
    __syncthreads();

    const float* pw = g_pwd + ((size_t)b*HWP + ij)*KK2;
    float w[KK2]; float ssum = 0.f;
#pragma unroll
    for (int di=0; di<5; di++) {
#pragma unroll
        for (int dj=0; dj<5; dj++) {
            const __half* np = Kh + ((ty+di)*36 + (tx+dj))*40;
            float s = 0.f;
#pragma unroll
            for (int v=0; v<4; v++) {
                uint4 r = *(const uint4*)(np + v*8);
                float2 f0 = __half22float2(*(__half2*)&r.x);
                float2 f1 = __half22float2(*(__half2*)&r.y);
                float2 f2 = __half22float2(*(__half2*)&r.z);
                float2 f3 = __half22float2(*(__half2*)&r.w);
                s = fmaf(q[v*8+0], f0.x, s);
                s = fmaf(q[v*8+1], f0.y, s);
                s = fmaf(q[v*8+2], f1.x, s);
                s = fmaf(q[v*8+3], f1.y, s);
                s = fmaf(q[v*8+4], f2.x, s);
                s = fmaf(q[v*8+5], f2.y, s);
                s = fmaf(q[v*8+6], f3.x, s);
                s = fmaf(q[v*8+7], f3.y, s);
            }
            int kk = di*5+dj;
            w[kk] = __expf(s * SCALE) * pw[kk];
            ssum += w[kk];
        }
    }
    const float inv = 1.f / fmaxf(ssum, 1e-30f);

    float out[32];
#pragma unroll
    for (int v=0;v<32;v++) out[v] = 0.f;
#pragma unroll
    for (int di=0; di<5; di++) {
#pragma unroll
        for (int dj=0; dj<5; dj++) {
            float wk = w[di*5+dj] * inv;
            const __half* np = Vh + ((ty+di)*36 + (tx+dj))*40;
#pragma unroll
            for (int v=0; v<4; v++) {
                uint4 r = *(const uint4*)(np + v*8);
                float2 f0 = __half22float2(*(__half2*)&r.x);
                float2 f1 = __half22float2(*(__half2*)&r.y);
                float2 f2 = __half22float2(*(__half2*)&r.z);
                float2 f3 = __half22float2(*(__half2*)&r.w);
                out[v*8+0] = fmaf(wk, f0.x, out[v*8+0]);
                out[v*8+1] = fmaf(wk, f0.y, out[v*8+1]);
                out[v*8+2] = fmaf(wk, f1.x, out[v*8+2]);
                out[v*8+3] = fmaf(wk, f1.y, out[v*8+3]);
                out[v*8+4] = fmaf(wk, f2.x, out[v*8+4]);
                out[v*8+5] = fmaf(wk, f2.y, out[v*8+5]);
                out[v*8+6] = fmaf(wk, f3.x, out[v*8+6]);
                out[v*8+7] = fmaf(wk, f3.y, out[v*8+7]);
            }
        }
    }
    float* ag = g_agg + ((size_t)b*HWP + ij)*CC + h*HDD;
#pragma unroll
    for (int v=0; v<8; v++)
        *(float4*)(ag + v*4) = make_float4(out[v*4], out[v*4+1],
                                           out[v*4+2], out[v*4+3]);
}

// ============================================================
// Kernel 4: proj GEMM via WMMA fp16 + free BCHW transpose store.
// A: g_agg staged+converted fp16 smem (row_major m,k).
// B: w_proj staged fp16 (row_major k,n). D col_major ld=HWP -> BCHW.
// ============================================================
__global__ void __launch_bounds__(256, 2)
k_proj_wmma(const float* __restrict__ w_proj, const float* __restrict__ b_proj,
            float* __restrict__ out)
{
    extern __shared__ char smraw[];
    float*  bias_s = (float*)smraw;                    // [16][132]
    __half* As     = (__half*)(smraw + 16*132*4);      // [m=128][k=128] ld LDH
    __half* Bs     = As + 128*LDH;                     // [k=128][n=128] ld LDH

    const int tid = threadIdx.x;
    const int wid = tid >> 5;
    const int wm  = wid & 3;
    const int wn  = wid >> 2;
    const int p0  = blockIdx.x * 128;
    const int b   = p0 / HWP;
    const int ij0 = p0 % HWP;

    const float* ab = g_agg + (size_t)p0 * CC;
#pragma unroll
    for (int it = 0; it < 16; it++) {
        int idx = tid + it*256;
        int m = idx >> 5, k4 = idx & 31;
        *(uint2*)(As + m*LDH + k4*4) =
            f4toh4(*(const float4*)(ab + (size_t)m*CC + k4*4));
    }
#pragma unroll
    for (int it = 0; it < 16; it++) {
        int idx = tid + it*256;
        int k = idx >> 5, n4 = idx & 31;
        *(uint2*)(Bs + k*LDH + n4*4) =
            f4toh4(*(const float4*)(w_proj + k*CC + n4*4));
    }
    if (tid < 128) {
        float bv = b_proj[tid];
#pragma unroll
        for (int r = 0; r < 16; r++) bias_s[r*132 + tid] = bv;
    }
    __syncthreads();

    wmma::fragment<wmma::accumulator, 16,16,16, float> acc[2][4];
#pragma unroll
    for (int mi = 0; mi < 2; mi++)
#pragma unroll
        for (int ni = 0; ni < 4; ni++)
            wmma::load_matrix_sync(acc[mi][ni], bias_s + wn*64 + ni*16,
                                   132, wmma::mem_row_major);

#pragma unroll
    for (int k0 = 0; k0 < CC; k0 += 16) {
        wmma::fragment<wmma::matrix_a, 16,16,16, __half, wmma::row_major> a[2];
#pragma unroll
        for (int mi = 0; mi < 2; mi++)
            wmma::load_matrix_sync(a[mi], As + (wm*32 + mi*16)*LDH + k0, LDH);
        wmma::fragment<wmma::matrix_b, 16,16,16, __half, wmma::row_major> bf[4];
#pragma unroll
        for (int ni = 0; ni < 4; ni++)
            wmma::load_matrix_sync(bf[ni], Bs + k0*LDH + wn*64 + ni*16, LDH);
#pragma unroll
        for (int mi = 0; mi < 2; mi++)
#pragma unroll
            for (int ni = 0; ni < 4; ni++)
                wmma::mma_sync(acc[mi][ni], a[mi], bf[ni], acc[mi][ni]);
    }

    float* ob = out + (size_t)b*CC*HWP + ij0;
#pragma unroll
    for (int mi = 0; mi < 2; mi++)
#pragma unroll
        for (int ni = 0; ni < 4; ni++) {
            int n0 = wn*64 + ni*16;
            int m0 = wm*32 + mi*16;
            wmma::store_matrix_sync(ob + (size_t)n0*HWP + m0, acc[mi][ni],
                                    HWP, wmma::mem_col_major);
        }
}

// ============================================================
extern "C" void kernel_launch(void* const* d_in, const int* in_sizes, int n_in,
                              void* d_out, int out_size)
{
    const float* x      = (const float*)d_in[0];
    const float* sims   = (const float*)d_in[1];
    const float* w_qk   = (const float*)d_in[2];
    const float* b_qk   = (const float*)d_in[3];
    const float* w_v    = (const float*)d_in[4];
    const float* b_v    = (const float*)d_in[5];
    const float* w_proj = (const float*)d_in[6];
    const float* b_proj = (const float*)d_in[7];
    float* out = (float*)d_out;

    cudaFuncSetAttribute(k_qkv_wmma,  cudaFuncAttributeMaxDynamicSharedMemorySize, GEMM_SMEM);
    cudaFuncSetAttribute(k_pwd,       cudaFuncAttributeMaxDynamicSharedMemorySize, 432*36*4);
    cudaFuncSetAttribute(k_attn,      cudaFuncAttributeMaxDynamicSharedMemorySize, ATT_SMEM);
    cudaFuncSetAttribute(k_proj_wmma, cudaFuncAttributeMaxDynamicSharedMemorySize, GEMM_SMEM);

    k_qkv_wmma <<<NPIX/128, 256, GEMM_SMEM>>>(x, w_qk, b_qk, w_v, b_v);
    k_pwd      <<<dim3(WW/32, HH/8, BB),     dim3(32,8), 432*36*4>>>(sims);
    k_attn     <<<dim3(WW/32, HH/8, BB*NHH), dim3(32,8), ATT_SMEM>>>();
    k_proj_wmma<<<NPIX/128, 256, GEMM_SMEM>>>(w_proj, b_proj, out);
}

// round 8
// speedup vs baseline: 1.9405x; 1.0258x over previous
#include <cuda_runtime.h>
#include <mma.h>
#include <cuda_fp16.h>
#include <math.h>

using namespace nvcuda;

#define BB 8
#define CC 128
#define HH 128
#define WW 128
#define NHH 4
#define HDD 32
#define SG2 256
#define HWP (HH*WW)      // 16384
#define NPIX (BB*HWP)    // 131072
#define KK2 25
#define SCALE 0.17677669529663687f   // 1/sqrt(32)

// ---- scratch (static device arrays; no runtime allocation) ----
static __device__ __align__(16) __half g_q[(size_t)NPIX*CC];   // [(b*NH+h)*HW+ij]*HD+d
static __device__ __align__(16) __half g_k[(size_t)NPIX*CC];
static __device__ __align__(16) __half g_v[(size_t)NPIX*CC];
static __device__ __align__(16) __half g_agg[(size_t)NPIX*CC]; // [p*128 + c]
static __device__ float g_pwd[(size_t)NPIX*KK2];               // [p*25 + k]

#define LDH 136                       // fp16 smem row stride (halfs)

__device__ __forceinline__ uint2 f4toh4(float4 v) {
    __half2 lo = __floats2half2_rn(v.x, v.y);
    __half2 hi = __floats2half2_rn(v.z, v.w);
    uint2 r;
    r.x = *(unsigned*)&lo;
    r.y = *(unsigned*)&hi;
    return r;
}

// ============================================================
// Kernel 1: QKV GEMM via WMMA fp16 (fp32 acc), fp16 outputs.
// A: x tile staged fp16 ONCE (col_major m=pix,k=chan).
// B: per-N-pass weight tile staged fp16 (row_major k,n).
// Epilogue: acc -> per-warp smem scratch -> half8 uint4 stores.
// ============================================================
// smem: bias[16][132] f32 | A[128][LDH] h | B[128][LDH] h | scratch 8*16*20 f32
#define QKV_SMEM (16*132*4 + 2*128*LDH*2 + 8*16*20*4)   // 88320 B -> 2 blocks/SM

__global__ void __launch_bounds__(256, 2)
k_qkv_wmma(const float* __restrict__ x, const float* __restrict__ w_qk,
           const float* __restrict__ b_qk, const float* __restrict__ w_v,
           const float* __restrict__ b_v)
{
    extern __shared__ char smraw[];
    float*  bias_s = (float*)smraw;                    // [16][132]
    __half* As     = (__half*)(smraw + 16*132*4);      // [k=128][m=128] ld LDH
    __half* Bs     = As + 128*LDH;                     // [k=128][n=128] ld LDH
    float*  scr_all= (float*)(smraw + 16*132*4 + 2*128*LDH*2);

    const int tid = threadIdx.x;
    const int wid = tid >> 5;
    const int lane = tid & 31;
    const int wm  = wid & 3;        // m quarter  (32 pixels)
    const int wn  = wid >> 2;       // n half     (64 outputs)
    const int p0  = blockIdx.x * 128;
    const int b   = p0 / HWP;
    const int ij0 = p0 % HWP;
    const float* xb = x + (size_t)b*CC*HWP + ij0;
    float* scr = scr_all + wid*16*20;

    // stage A once: As[k*LDH + m] = fp16(x[b, k, ij0+m])
#pragma unroll
    for (int it = 0; it < 16; it++) {
        int idx = tid + it*256;            // 4096 float4
        int k = idx >> 5, m4 = idx & 31;
        *(uint2*)(As + k*LDH + m4*4) =
            f4toh4(*(const float4*)(xb + (size_t)k*HWP + m4*4));
    }

    for (int nt = 0; nt < 3; nt++) {
        __syncthreads();
#pragma unroll
        for (int it = 0; it < 16; it++) {
            int idx = tid + it*256;
            int k = idx >> 5, n4 = idx & 31;
            const float* src = (nt < 2) ? (w_qk + k*2*CC + nt*128 + n4*4)
                                        : (w_v  + k*CC  + n4*4);
            *(uint2*)(Bs + k*LDH + n4*4) = f4toh4(*(const float4*)src);
        }
        if (tid < 128) {
            float bv = (nt < 2) ? b_qk[nt*128 + tid] : b_v[tid];
#pragma unroll
            for (int r = 0; r < 16; r++) bias_s[r*132 + tid] = bv;
        }
        __syncthreads();

        wmma::fragment<wmma::accumulator, 16,16,16, float> acc[2][4];
#pragma unroll
        for (int mi = 0; mi < 2; mi++)
#pragma unroll
            for (int ni = 0; ni < 4; ni++)
                wmma::load_matrix_sync(acc[mi][ni], bias_s + wn*64 + ni*16,
                                       132, wmma::mem_row_major);

#pragma unroll
        for (int k0 = 0; k0 < CC; k0 += 16) {
            wmma::fragment<wmma::matrix_a, 16,16,16, __half, wmma::col_major> a[2];
#pragma unroll
            for (int mi = 0; mi < 2; mi++)
                wmma::load_matrix_sync(a[mi], As + k0*LDH + wm*32 + mi*16, LDH);
            wmma::fragment<wmma::matrix_b, 16,16,16, __half, wmma::row_major> bf[4];
#pragma unroll
            for (int ni = 0; ni < 4; ni++)
                wmma::load_matrix_sync(bf[ni], Bs + k0*LDH + wn*64 + ni*16, LDH);
#pragma unroll
            for (int mi = 0; mi < 2; mi++)
#pragma unroll
                for (int ni = 0; ni < 4; ni++)
                    wmma::mma_sync(acc[mi][ni], a[mi], bf[ni], acc[mi][ni]);
        }

        __half* dstbase = (nt == 0) ? g_q : (nt == 1) ? g_k : g_v;
        const int r = lane >> 1, c = (lane & 1) * 8;   // 16 rows x 2 col-halves
#pragma unroll
        for (int mi = 0; mi < 2; mi++)
#pragma unroll
            for (int ni = 0; ni < 4; ni++) {
                wmma::store_matrix_sync(scr, acc[mi][ni], 20, wmma::mem_row_major);
                __syncwarp();
                float4 f0 = *(const float4*)(scr + r*20 + c);
                float4 f1 = *(const float4*)(scr + r*20 + c + 4);
                uint2 h0 = f4toh4(f0), h1 = f4toh4(f1);
                uint4 o = make_uint4(h0.x, h0.y, h1.x, h1.y);
                int n0 = wn*64 + ni*16;
                int head = n0 >> 5, d0 = n0 & 31;
                __half* dst = dstbase +
                    ((size_t)(b*NHH + head)*HWP + ij0 + wm*32 + mi*16 + r)*HDD + d0 + c;
                *(uint4*)dst = o;
                __syncwarp();
            }
    }
}

// ============================================================
// Kernel 2: pwd[p, k] = sum_s sims[p,s] * sims[p+off_k, s]
// 16x32 tile, 20x36 halo (amplification 1.41x), 512 threads.
// ============================================================
#define PWD_SMEM (720*36*4)   // 103680 B -> 1 block/SM

__global__ void __launch_bounds__(512)
k_pwd(const float* __restrict__ sims)
{
    extern __shared__ float Ss[];  // [720 halo pixels][36]
    const int b  = blockIdx.z;
    const int i0 = blockIdx.y * 16;
    const int j0 = blockIdx.x * 32;
    const int tx = threadIdx.x, ty = threadIdx.y;
    const int tid = ty*32 + tx;
    const float* sb = sims + (size_t)b*HWP*SG2;

    float acc[KK2];
#pragma unroll
    for (int k=0;k<KK2;k++) acc[k] = 0.f;

    for (int scc = 0; scc < SG2; scc += 32) {
        __syncthreads();
        for (int idx = tid; idx < 720*8; idx += 512) {
            int pix = idx >> 3, v = idx & 7;
            int hr = pix / 36, hc = pix - hr*36;
            int gi = i0 - 2 + hr, gj = j0 - 2 + hc;
            float4 val = make_float4(0.f,0.f,0.f,0.f);
            if ((unsigned)gi < HH && (unsigned)gj < WW)
                val = *(const float4*)(sb + ((size_t)gi*WW + gj)*SG2 + scc + v*4);
            *(float4*)(Ss + pix*36 + v*4) = val;
        }
        __syncthreads();

        float own[32];
        const float* op = Ss + ((ty+2)*36 + (tx+2))*36;
#pragma unroll
        for (int v=0; v<8; v++) {
            float4 t = *(const float4*)(op + v*4);
            own[v*4]=t.x; own[v*4+1]=t.y; own[v*4+2]=t.z; own[v*4+3]=t.w;
        }
#pragma unroll
        for (int di=0; di<5; di++) {
#pragma unroll
            for (int dj=0; dj<5; dj++) {
                const float* np = Ss + ((ty+di)*36 + (tx+dj))*36;
                float s = 0.f;
#pragma unroll
                for (int v=0; v<8; v++) {
                    float4 t = *(const float4*)(np + v*4);
                    s = fmaf(own[v*4],   t.x, s);
                    s = fmaf(own[v*4+1], t.y, s);
                    s = fmaf(own[v*4+2], t.z, s);
                    s = fmaf(own[v*4+3], t.w, s);
                }
                acc[di*5+dj] += s;
            }
        }
    }
    const size_t p = (size_t)b*HWP + (size_t)(i0+ty)*WW + (j0+tx);
#pragma unroll
    for (int k=0;k<KK2;k++) g_pwd[p*KK2 + k] = acc[k];
}

// ============================================================
// Kernel 3: attention + V aggregation; all tensors fp16 in global.
// Staging = raw uint4 copies (no conversion). Math fp32.
// exp needs no max-subtraction (denominator cancels vs pwd renorm).
// ============================================================
#define ATT_SMEM (2*432*40*2)   // Kh + Vh, 69120 B -> 2 blocks/SM

__global__ void __launch_bounds__(256, 2)
k_attn()
{
    extern __shared__ __half sh[];
    __half* Kh = sh;              // [432][40]
    __half* Vh = sh + 432*40;

    const int bh = blockIdx.z;
    const int b  = bh >> 2;
    const int h  = bh & 3;
    const int i0 = blockIdx.y * 8;
    const int j0 = blockIdx.x * 32;
    const int tx = threadIdx.x, ty = threadIdx.y;
    const int tid = ty*32 + tx;
    const size_t headoff = (size_t)bh*HWP*HDD;
    const int ij = (i0+ty)*WW + (j0+tx);

    const __half* kb = g_k + headoff;
    const __half* vb = g_v + headoff;
    for (int idx = tid; idx < 432*4; idx += 256) {
        int pix = idx >> 2, v = idx & 3;
        int hr = pix / 36, hc = pix - hr*36;
        int gi = i0 - 2 + hr, gj = j0 - 2 + hc;
        uint4 kp = make_uint4(0,0,0,0), vp = make_uint4(0,0,0,0);
        if ((unsigned)gi < HH && (unsigned)gj < WW) {
            size_t off = (size_t)(gi*WW + gj)*HDD + v*8;
            kp = *(const uint4*)(kb + off);
            vp = *(const uint4*)(vb + off);
        }
        *(uint4*)(Kh + pix*40 + v*8) = kp;
        *(uint4*)(Vh + pix*40 + v*8) = vp;
    }

    float q[32];
    {
        const __half* qp = g_q + headoff + (size_t)ij*HDD;
#pragma unroll
        for (int v=0; v<4; v++) {
            uint4 r = *(const uint4*)(qp + v*8);
            float2 f0 = __half22float2(*(__half2*)&r.x);
            float2 f1 = __half22float2(*(__half2*)&r.y);
            float2 f2 = __half22float2(*(__half2*)&r.z);
            float2 f3 = __half22float2(*(__half2*)&r.w);
            q[v*8+0]=f0.x; q[v*8+1]=f0.y; q[v*8+2]=f1.x; q[v*8+3]=f1.y;
            q[v*8+4]=f2.x; q[v*8+5]=f2.y; q[v*8+6]=f3.x; q[v*8+7]=f3.y;
        }
    }
    __syncthreads();

    const float* pw = g_pwd + ((size_t)b*HWP + ij)*KK2;
    float w[KK2]; float ssum = 0.f;
#pragma unroll
    for (int di=0; di<5; di++) {
#pragma unroll
        for (int dj=0; dj<5; dj++) {
            const __half* np = Kh + ((ty+di)*36 + (tx+dj))*40;
            float s = 0.f;
#pragma unroll
            for (int v=0; v<4; v++) {
                uint4 r = *(const uint4*)(np + v*8);
                float2 f0 = __half22float2(*(__half2*)&r.x);
                float2 f1 = __half22float2(*(__half2*)&r.y);
                float2 f2 = __half22float2(*(__half2*)&r.z);
                float2 f3 = __half22float2(*(__half2*)&r.w);
                s = fmaf(q[v*8+0], f0.x, s);
                s = fmaf(q[v*8+1], f0.y, s);
                s = fmaf(q[v*8+2], f1.x, s);
                s = fmaf(q[v*8+3], f1.y, s);
                s = fmaf(q[v*8+4], f2.x, s);
                s = fmaf(q[v*8+5], f2.y, s);
                s = fmaf(q[v*8+6], f3.x, s);
                s = fmaf(q[v*8+7], f3.y, s);
            }
            int kk = di*5+dj;
            w[kk] = __expf(s * SCALE) * pw[kk];
            ssum += w[kk];
        }
    }
    const float inv = 1.f / fmaxf(ssum, 1e-30f);

    float out[32];
#pragma unroll
    for (int v=0;v<32;v++) out[v] = 0.f;
#pragma unroll
    for (int di=0; di<5; di++) {
#pragma unroll
        for (int dj=0; dj<5; dj++) {
            float wk = w[di*5+dj] * inv;
            const __half* np = Vh + ((ty+di)*36 + (tx+dj))*40;
#pragma unroll
            for (int v=0; v<4; v++) {
                uint4 r = *(const uint4*)(np + v*8);
                float2 f0 = __half22float2(*(__half2*)&r.x);
                float2 f1 = __half22float2(*(__half2*)&r.y);
                float2 f2 = __half22float2(*(__half2*)&r.z);
                float2 f3 = __half22float2(*(__half2*)&r.w);
                out[v*8+0] = fmaf(wk, f0.x, out[v*8+0]);
                out[v*8+1] = fmaf(wk, f0.y, out[v*8+1]);
                out[v*8+2] = fmaf(wk, f1.x, out[v*8+2]);
                out[v*8+3] = fmaf(wk, f1.y, out[v*8+3]);
                out[v*8+4] = fmaf(wk, f2.x, out[v*8+4]);
                out[v*8+5] = fmaf(wk, f2.y, out[v*8+5]);
                out[v*8+6] = fmaf(wk, f3.x, out[v*8+6]);
                out[v*8+7] = fmaf(wk, f3.y, out[v*8+7]);
            }
        }
    }
    __half* ag = g_agg + ((size_t)b*HWP + ij)*CC + h*HDD;
#pragma unroll
    for (int v=0; v<4; v++) {
        uint2 h0 = f4toh4(make_float4(out[v*8+0], out[v*8+1], out[v*8+2], out[v*8+3]));
        uint2 h1 = f4toh4(make_float4(out[v*8+4], out[v*8+5], out[v*8+6], out[v*8+7]));
        *(uint4*)(ag + v*8) = make_uint4(h0.x, h0.y, h1.x, h1.y);
    }
}

// ============================================================
// Kernel 4: proj GEMM via WMMA fp16 + free BCHW transpose store.
// A: raw uint4 copies from fp16 g_agg. B: w_proj staged fp16.
// D col_major ld=HWP -> BCHW fp32 output.
// ============================================================
#define PRJ_SMEM (16*132*4 + 2*128*LDH*2)   // 78080 B -> 2 blocks/SM

__global__ void __launch_bounds__(256, 2)
k_proj_wmma(const float* __restrict__ w_proj, const float* __restrict__ b_proj,
            float* __restrict__ out)
{
    extern __shared__ char smraw[];
    float*  bias_s = (float*)smraw;                    // [16][132]
    __half* As     = (__half*)(smraw + 16*132*4);      // [m=128][k=128] ld LDH
    __half* Bs     = As + 128*LDH;                     // [k=128][n=128] ld LDH

    const int tid = threadIdx.x;
    const int wid = tid >> 5;
    const int wm  = wid & 3;
    const int wn  = wid >> 2;
    const int p0  = blockIdx.x * 128;
    const int b   = p0 / HWP;
    const int ij0 = p0 % HWP;

    const __half* ab = g_agg + (size_t)p0 * CC;
#pragma unroll
    for (int it = 0; it < 8; it++) {
        int idx = tid + it*256;            // 2048 uint4
        int m = idx >> 4, k8 = idx & 15;
        *(uint4*)(As + m*LDH + k8*8) = *(const uint4*)(ab + (size_t)m*CC + k8*8);
    }
#pragma unroll
    for (int it = 0; it < 16; it++) {
        int idx = tid + it*256;
        int k = idx >> 5, n4 = idx & 31;
        *(uint2*)(Bs + k*LDH + n4*4) =
            f4toh4(*(const float4*)(w_proj + k*CC + n4*4));
    }
    if (tid < 128) {
        float bv = b_proj[tid];
#pragma unroll
        for (int r = 0; r < 16; r++) bias_s[r*132 + tid] = bv;
    }
    __syncthreads();

    wmma::fragment<wmma::accumulator, 16,16,16, float> acc[2][4];
#pragma unroll
    for (int mi = 0; mi < 2; mi++)
#pragma unroll
        for (int ni = 0; ni < 4; ni++)
            wmma::load_matrix_sync(acc[mi][ni], bias_s + wn*64 + ni*16,
                                   132, wmma::mem_row_major);

#pragma unroll
    for (int k0 = 0; k0 < CC; k0 += 16) {
        wmma::fragment<wmma::matrix_a, 16,16,16, __half, wmma::row_major> a[2];
#pragma unroll
        for (int mi = 0; mi < 2; mi++)
            wmma::load_matrix_sync(a[mi], As + (wm*32 + mi*16)*LDH + k0, LDH);
        wmma::fragment<wmma::matrix_b, 16,16,16, __half, wmma::row_major> bf[4];
#pragma unroll
        for (int ni = 0; ni < 4; ni++)
            wmma::load_matrix_sync(bf[ni], Bs + k0*LDH + wn*64 + ni*16, LDH);
#pragma unroll
        for (int mi = 0; mi < 2; mi++)
#pragma unroll
            for (int ni = 0; ni < 4; ni++)
                wmma::mma_sync(acc[mi][ni], a[mi], bf[ni], acc[mi][ni]);
    }

    float* ob = out + (size_t)b*CC*HWP + ij0;
#pragma unroll
    for (int mi = 0; mi < 2; mi++)
#pragma unroll
        for (int ni = 0; ni < 4; ni++) {
            int n0 = wn*64 + ni*16;
            int m0 = wm*32 + mi*16;
            wmma::store_matrix_sync(ob + (size_t)n0*HWP + m0, acc[mi][ni],
                                    HWP, wmma::mem_col_major);
        }
}

// ============================================================
extern "C" void kernel_launch(void* const* d_in, const int* in_sizes, int n_in,
                              void* d_out, int out_size)
{
    const float* x      = (const float*)d_in[0];
    const float* sims   = (const float*)d_in[1];
    const float* w_qk   = (const float*)d_in[2];
    const float* b_qk   = (const float*)d_in[3];
    const float* w_v    = (const float*)d_in[4];
    const float* b_v    = (const float*)d_in[5];
    const float* w_proj = (const float*)d_in[6];
    const float* b_proj = (const float*)d_in[7];
    float* out = (float*)d_out;

    cudaFuncSetAttribute(k_qkv_wmma,  cudaFuncAttributeMaxDynamicSharedMemorySize, QKV_SMEM);
    cudaFuncSetAttribute(k_pwd,       cudaFuncAttributeMaxDynamicSharedMemorySize, PWD_SMEM);
    cudaFuncSetAttribute(k_attn,      cudaFuncAttributeMaxDynamicSharedMemorySize, ATT_SMEM);
    cudaFuncSetAttribute(k_proj_wmma, cudaFuncAttributeMaxDynamicSharedMemorySize, PRJ_SMEM);

    k_qkv_wmma <<<NPIX/128, 256, QKV_SMEM>>>(x, w_qk, b_qk, w_v, b_v);
    k_pwd      <<<dim3(WW/32, HH/16, BB),    dim3(32,16), PWD_SMEM>>>(sims);
    k_attn     <<<dim3(WW/32, HH/8, BB*NHH), dim3(32,8),  ATT_SMEM>>>();
    k_proj_wmma<<<NPIX/128, 256, PRJ_SMEM>>>(w_proj, b_proj, out);
}

// round 9
// speedup vs baseline: 2.0588x; 1.0610x over previous
#include <cuda_runtime.h>
#include <mma.h>
#include <cuda_fp16.h>
#include <math.h>

using namespace nvcuda;

#define BB 8
#define CC 128
#define HH 128
#define WW 128
#define NHH 4
#define HDD 32
#define SG2 256
#define HWP (HH*WW)      // 16384
#define NPIX (BB*HWP)    // 131072
#define KK2 25
#define SCALE 0.17677669529663687f   // 1/sqrt(32)

// ---- scratch (static device arrays; no runtime allocation) ----
static __device__ __align__(16) __half g_q[(size_t)NPIX*CC];
static __device__ __align__(16) __half g_k[(size_t)NPIX*CC];
static __device__ __align__(16) __half g_v[(size_t)NPIX*CC];
static __device__ __align__(16) __half g_agg[(size_t)NPIX*CC];
static __device__ __align__(16) __half g_pwd[(size_t)NPIX*KK2];  // x256 scale (cancels)

#define LDH 136                       // fp16 smem row stride (halfs)

__device__ __forceinline__ uint2 f4toh4(float4 v) {
    __half2 lo = __floats2half2_rn(v.x, v.y);
    __half2 hi = __floats2half2_rn(v.z, v.w);
    uint2 r;
    r.x = *(unsigned*)&lo;
    r.y = *(unsigned*)&hi;
    return r;
}

// ============================================================
// Kernel 1: QKV GEMM via WMMA fp16 (fp32 acc), fp16 outputs via
// fragment-level f32->f16 conversion (no smem bounce, no syncs).
// ============================================================
#define QKV_SMEM (16*132*4 + 2*128*LDH*2)   // 78080 B -> 2 blocks/SM

__global__ void __launch_bounds__(256, 2)
k_qkv_wmma(const float* __restrict__ x, const float* __restrict__ w_qk,
           const float* __restrict__ b_qk, const float* __restrict__ w_v,
           const float* __restrict__ b_v)
{
    extern __shared__ char smraw[];
    float*  bias_s = (float*)smraw;                    // [16][132]
    __half* As     = (__half*)(smraw + 16*132*4);      // [k=128][m=128] ld LDH
    __half* Bs     = As + 128*LDH;                     // [k=128][n=128] ld LDH

    const int tid = threadIdx.x;
    const int wid = tid >> 5;
    const int wm  = wid & 3;        // m quarter  (32 pixels)
    const int wn  = wid >> 2;       // n half     (64 outputs)
    const int p0  = blockIdx.x * 128;
    const int b   = p0 / HWP;
    const int ij0 = p0 % HWP;
    const float* xb = x + (size_t)b*CC*HWP + ij0;

    // stage A once: As[k*LDH + m] = fp16(x[b, k, ij0+m])
#pragma unroll
    for (int it = 0; it < 16; it++) {
        int idx = tid + it*256;            // 4096 float4
        int k = idx >> 5, m4 = idx & 31;
        *(uint2*)(As + k*LDH + m4*4) =
            f4toh4(*(const float4*)(xb + (size_t)k*HWP + m4*4));
    }

    for (int nt = 0; nt < 3; nt++) {
        __syncthreads();
#pragma unroll
        for (int it = 0; it < 16; it++) {
            int idx = tid + it*256;
            int k = idx >> 5, n4 = idx & 31;
            const float* src = (nt < 2) ? (w_qk + k*2*CC + nt*128 + n4*4)
                                        : (w_v  + k*CC  + n4*4);
            *(uint2*)(Bs + k*LDH + n4*4) = f4toh4(*(const float4*)src);
        }
        if (tid < 128) {
            float bv = (nt < 2) ? b_qk[nt*128 + tid] : b_v[tid];
#pragma unroll
            for (int r = 0; r < 16; r++) bias_s[r*132 + tid] = bv;
        }
        __syncthreads();

        wmma::fragment<wmma::accumulator, 16,16,16, float> acc[2][4];
#pragma unroll
        for (int mi = 0; mi < 2; mi++)
#pragma unroll
            for (int ni = 0; ni < 4; ni++)
                wmma::load_matrix_sync(acc[mi][ni], bias_s + wn*64 + ni*16,
                                       132, wmma::mem_row_major);

#pragma unroll
        for (int k0 = 0; k0 < CC; k0 += 16) {
            wmma::fragment<wmma::matrix_a, 16,16,16, __half, wmma::col_major> a[2];
#pragma unroll
            for (int mi = 0; mi < 2; mi++)
                wmma::load_matrix_sync(a[mi], As + k0*LDH + wm*32 + mi*16, LDH);
            wmma::fragment<wmma::matrix_b, 16,16,16, __half, wmma::row_major> bf[4];
#pragma unroll
            for (int ni = 0; ni < 4; ni++)
                wmma::load_matrix_sync(bf[ni], Bs + k0*LDH + wn*64 + ni*16, LDH);
#pragma unroll
            for (int mi = 0; mi < 2; mi++)
#pragma unroll
                for (int ni = 0; ni < 4; ni++)
                    wmma::mma_sync(acc[mi][ni], a[mi], bf[ni], acc[mi][ni]);
        }

        __half* dstbase = (nt == 0) ? g_q : (nt == 1) ? g_k : g_v;
#pragma unroll
        for (int mi = 0; mi < 2; mi++)
#pragma unroll
            for (int ni = 0; ni < 4; ni++) {
                // f32 acc -> f16 acc fragment (identical coordinate mapping)
                wmma::fragment<wmma::accumulator, 16,16,16, __half> hacc;
#pragma unroll
                for (int e = 0; e < 8; e++)
                    hacc.x[e] = __float2half(acc[mi][ni].x[e]);
                int n0 = wn*64 + ni*16;
                int head = n0 >> 5, d0 = n0 & 31;
                __half* dst = dstbase +
                    ((size_t)(b*NHH + head)*HWP + ij0 + wm*32 + mi*16)*HDD + d0;
                wmma::store_matrix_sync(dst, hacc, HDD, wmma::mem_row_major);
            }
    }
}

// ============================================================
// Kernel 2: pwd = sum_s sims[p,s]*sims[p+off,s], fp16 halos.
// 16x32 tile, 20x36 halo, 512 threads. sims scaled x16 at cvt
// (pwd x256 common factor cancels in the weight renorm).
// ============================================================
#define PWD_SMEM (720*40*2)   // 57600 B

__global__ void __launch_bounds__(512)
k_pwd(const float* __restrict__ sims)
{
    extern __shared__ __half Sh[];  // [720 halo pixels][40]
    const int b  = blockIdx.z;
    const int i0 = blockIdx.y * 16;
    const int j0 = blockIdx.x * 32;
    const int tx = threadIdx.x, ty = threadIdx.y;
    const int tid = ty*32 + tx;
    const float* sb = sims + (size_t)b*HWP*SG2;

    float acc[KK2];
#pragma unroll
    for (int k=0;k<KK2;k++) acc[k] = 0.f;

    for (int scc = 0; scc < SG2; scc += 32) {
        __syncthreads();
        for (int idx = tid; idx < 720*4; idx += 512) {
            int pix = idx >> 2, v = idx & 3;
            int hr = pix / 36, hc = pix - hr*36;
            int gi = i0 - 2 + hr, gj = j0 - 2 + hc;
            uint4 o = make_uint4(0,0,0,0);
            if ((unsigned)gi < HH && (unsigned)gj < WW) {
                const float* src = sb + ((size_t)gi*WW + gj)*SG2 + scc + v*8;
                float4 f0 = *(const float4*)src;
                float4 f1 = *(const float4*)(src + 4);
                f0.x*=16.f; f0.y*=16.f; f0.z*=16.f; f0.w*=16.f;
                f1.x*=16.f; f1.y*=16.f; f1.z*=16.f; f1.w*=16.f;
                uint2 h0 = f4toh4(f0), h1 = f4toh4(f1);
                o = make_uint4(h0.x, h0.y, h1.x, h1.y);
            }
            *(uint4*)(Sh + pix*40 + v*8) = o;
        }
        __syncthreads();

        float own[32];
        const __half* op = Sh + ((ty+2)*36 + (tx+2))*40;
#pragma unroll
        for (int v=0; v<4; v++) {
            uint4 r = *(const uint4*)(op + v*8);
            float2 f0 = __half22float2(*(__half2*)&r.x);
            float2 f1 = __half22float2(*(__half2*)&r.y);
            float2 f2 = __half22float2(*(__half2*)&r.z);
            float2 f3 = __half22float2(*(__half2*)&r.w);
            own[v*8+0]=f0.x; own[v*8+1]=f0.y; own[v*8+2]=f1.x; own[v*8+3]=f1.y;
            own[v*8+4]=f2.x; own[v*8+5]=f2.y; own[v*8+6]=f3.x; own[v*8+7]=f3.y;
        }
#pragma unroll
        for (int di=0; di<5; di++) {
#pragma unroll
            for (int dj=0; dj<5; dj++) {
                const __half* np = Sh + ((ty+di)*36 + (tx+dj))*40;
                float s = 0.f;
#pragma unroll
                for (int v=0; v<4; v++) {
                    uint4 r = *(const uint4*)(np + v*8);
                    float2 f0 = __half22float2(*(__half2*)&r.x);
                    float2 f1 = __half22float2(*(__half2*)&r.y);
                    float2 f2 = __half22float2(*(__half2*)&r.z);
                    float2 f3 = __half22float2(*(__half2*)&r.w);
                    s = fmaf(own[v*8+0], f0.x, s);
                    s = fmaf(own[v*8+1], f0.y, s);
                    s = fmaf(own[v*8+2], f1.x, s);
                    s = fmaf(own[v*8+3], f1.y, s);
                    s = fmaf(own[v*8+4], f2.x, s);
                    s = fmaf(own[v*8+5], f2.y, s);
                    s = fmaf(own[v*8+6], f3.x, s);
                    s = fmaf(own[v*8+7], f3.y, s);
                }
                acc[di*5+dj] += s;
            }
        }
    }
    const size_t p = (size_t)b*HWP + (size_t)(i0+ty)*WW + (j0+tx);
#pragma unroll
    for (int k=0;k<KK2;k++) g_pwd[p*KK2 + k] = __float2half(acc[k]);
}

// ============================================================
// Kernel 3: attention + V aggregation; all fp16 in global, fp32 math.
// ============================================================
#define ATT_SMEM (2*432*40*2)   // 69120 B -> 2 blocks/SM

__global__ void __launch_bounds__(256, 2)
k_attn()
{
    extern __shared__ __half sh[];
    __half* Kh = sh;              // [432][40]
    __half* Vh = sh + 432*40;

    const int bh = blockIdx.z;
    const int b  = bh >> 2;
    const int h  = bh & 3;
    const int i0 = blockIdx.y * 8;
    const int j0 = blockIdx.x * 32;
    const int tx = threadIdx.x, ty = threadIdx.y;
    const int tid = ty*32 + tx;
    const size_t headoff = (size_t)bh*HWP*HDD;
    const int ij = (i0+ty)*WW + (j0+tx);

    const __half* kb = g_k + headoff;
    const __half* vb = g_v + headoff;
    for (int idx = tid; idx < 432*4; idx += 256) {
        int pix = idx >> 2, v = idx & 3;
        int hr = pix / 36, hc = pix - hr*36;
        int gi = i0 - 2 + hr, gj = j0 - 2 + hc;
        uint4 kp = make_uint4(0,0,0,0), vp = make_uint4(0,0,0,0);
        if ((unsigned)gi < HH && (unsigned)gj < WW) {
            size_t off = (size_t)(gi*WW + gj)*HDD + v*8;
            kp = *(const uint4*)(kb + off);
            vp = *(const uint4*)(vb + off);
        }
        *(uint4*)(Kh + pix*40 + v*8) = kp;
        *(uint4*)(Vh + pix*40 + v*8) = vp;
    }

    float q[32];
    {
        const __half* qp = g_q + headoff + (size_t)ij*HDD;
#pragma unroll
        for (int v=0; v<4; v++) {
            uint4 r = *(const uint4*)(qp + v*8);
            float2 f0 = __half22float2(*(__half2*)&r.x);
            float2 f1 = __half22float2(*(__half2*)&r.y);
            float2 f2 = __half22float2(*(__half2*)&r.z);
            float2 f3 = __half22float2(*(__half2*)&r.w);
            q[v*8+0]=f0.x; q[v*8+1]=f0.y; q[v*8+2]=f1.x; q[v*8+3]=f1.y;
            q[v*8+4]=f2.x; q[v*8+5]=f2.y; q[v*8+6]=f3.x; q[v*8+7]=f3.y;
        }
    }
    __syncthreads();

    const __half* pw = g_pwd + ((size_t)b*HWP + ij)*KK2;
    float w[KK2]; float ssum = 0.f;
#pragma unroll
    for (int di=0; di<5; di++) {
#pragma unroll
        for (int dj=0; dj<5; dj++) {
            const __half* np = Kh + ((ty+di)*36 + (tx+dj))*40;
            float s = 0.f;
#pragma unroll
            for (int v=0; v<4; v++) {
                uint4 r = *(const uint4*)(np + v*8);
                float2 f0 = __half22float2(*(__half2*)&r.x);
                float2 f1 = __half22float2(*(__half2*)&r.y);
                float2 f2 = __half22float2(*(__half2*)&r.z);
                float2 f3 = __half22float2(*(__half2*)&r.w);
                s = fmaf(q[v*8+0], f0.x, s);
                s = fmaf(q[v*8+1], f0.y, s);
                s = fmaf(q[v*8+2], f1.x, s);
                s = fmaf(q[v*8+3], f1.y, s);
                s = fmaf(q[v*8+4], f2.x, s);
                s = fmaf(q[v*8+5], f2.y, s);
                s = fmaf(q[v*8+6], f3.x, s);
                s = fmaf(q[v*8+7], f3.y, s);
            }
            int kk = di*5+dj;
            w[kk] = __expf(s * SCALE) * __half2float(pw[kk]);
            ssum += w[kk];
        }
    }
    const float inv = 1.f / fmaxf(ssum, 1e-30f);

    float out[32];
#pragma unroll
    for (int v=0;v<32;v++) out[v] = 0.f;
#pragma unroll
    for (int di=0; di<5; di++) {
#pragma unroll
        for (int dj=0; dj<5; dj++) {
            float wk = w[di*5+dj] * inv;
            const __half* np = Vh + ((ty+di)*36 + (tx+dj))*40;
#pragma unroll
            for (int v=0; v<4; v++) {
                uint4 r = *(const uint4*)(np + v*8);
                float2 f0 = __half22float2(*(__half2*)&r.x);
                float2 f1 = __half22float2(*(__half2*)&r.y);
                float2 f2 = __half22float2(*(__half2*)&r.z);
                float2 f3 = __half22float2(*(__half2*)&r.w);
                out[v*8+0] = fmaf(wk, f0.x, out[v*8+0]);
                out[v*8+1] = fmaf(wk, f0.y, out[v*8+1]);
                out[v*8+2] = fmaf(wk, f1.x, out[v*8+2]);
                out[v*8+3] = fmaf(wk, f1.y, out[v*8+3]);
                out[v*8+4] = fmaf(wk, f2.x, out[v*8+4]);
                out[v*8+5] = fmaf(wk, f2.y, out[v*8+5]);
                out[v*8+6] = fmaf(wk, f3.x, out[v*8+6]);
                out[v*8+7] = fmaf(wk, f3.y, out[v*8+7]);
            }
        }
    }
    __half* ag = g_agg + ((size_t)b*HWP + ij)*CC + h*HDD;
#pragma unroll
    for (int v=0; v<4; v++) {
        uint2 h0 = f4toh4(make_float4(out[v*8+0], out[v*8+1], out[v*8+2], out[v*8+3]));
        uint2 h1 = f4toh4(make_float4(out[v*8+4], out[v*8+5], out[v*8+6], out[v*8+7]));
        *(uint4*)(ag + v*8) = make_uint4(h0.x, h0.y, h1.x, h1.y);
    }
}

// ============================================================
// Kernel 4: proj GEMM via WMMA fp16 + free BCHW transpose store.
// ============================================================
#define PRJ_SMEM (16*132*4 + 2*128*LDH*2)   // 78080 B -> 2 blocks/SM

__global__ void __launch_bounds__(256, 2)
k_proj_wmma(const float* __restrict__ w_proj, const float* __restrict__ b_proj,
            float* __restrict__ out)
{
    extern __shared__ char smraw[];
    float*  bias_s = (float*)smraw;                    // [16][132]
    __half* As     = (__half*)(smraw + 16*132*4);      // [m=128][k=128] ld LDH
    __half* Bs     = As + 128*LDH;                     // [k=128][n=128] ld LDH

    const int tid = threadIdx.x;
    const int wid = tid >> 5;
    const int wm  = wid & 3;
    const int wn  = wid >> 2;
    const int p0  = blockIdx.x * 128;
    const int b   = p0 / HWP;
    const int ij0 = p0 % HWP;

    const __half* ab = g_agg + (size_t)p0 * CC;
#pragma unroll
    for (int it = 0; it < 8; it++) {
        int idx = tid + it*256;            // 2048 uint4
        int m = idx >> 4, k8 = idx & 15;
        *(uint4*)(As + m*LDH + k8*8) = *(const uint4*)(ab + (size_t)m*CC + k8*8);
    }
#pragma unroll
    for (int it = 0; it < 16; it++) {
        int idx = tid + it*256;
        int k = idx >> 5, n4 = idx & 31;
        *(uint2*)(Bs + k*LDH + n4*4) =
            f4toh4(*(const float4*)(w_proj + k*CC + n4*4));
    }
    if (tid < 128) {
        float bv = b_proj[tid];
#pragma unroll
        for (int r = 0; r < 16; r++) bias_s[r*132 + tid] = bv;
    }
    __syncthreads();

    wmma::fragment<wmma::accumulator, 16,16,16, float> acc[2][4];
#pragma unroll
    for (int mi = 0; mi < 2; mi++)
#pragma unroll
        for (int ni = 0; ni < 4; ni++)
            wmma::load_matrix_sync(acc[mi][ni], bias_s + wn*64 + ni*16,
                                   132, wmma::mem_row_major);

#pragma unroll
    for (int k0 = 0; k0 < CC; k0 += 16) {
        wmma::fragment<wmma::matrix_a, 16,16,16, __half, wmma::row_major> a[2];
#pragma unroll
        for (int mi = 0; mi < 2; mi++)
            wmma::load_matrix_sync(a[mi], As + (wm*32 + mi*16)*LDH + k0, LDH);
        wmma::fragment<wmma::matrix_b, 16,16,16, __half, wmma::row_major> bf[4];
#pragma unroll
        for (int ni = 0; ni < 4; ni++)
            wmma::load_matrix_sync(bf[ni], Bs + k0*LDH + wn*64 + ni*16, LDH);
#pragma unroll
        for (int mi = 0; mi < 2; mi++)
#pragma unroll
            for (int ni = 0; ni < 4; ni++)
                wmma::mma_sync(acc[mi][ni], a[mi], bf[ni], acc[mi][ni]);
    }

    float* ob = out + (size_t)b*CC*HWP + ij0;
#pragma unroll
    for (int mi = 0; mi < 2; mi++)
#pragma unroll
        for (int ni = 0; ni < 4; ni++) {
            int n0 = wn*64 + ni*16;
            int m0 = wm*32 + mi*16;
            wmma::store_matrix_sync(ob + (size_t)n0*HWP + m0, acc[mi][ni],
                                    HWP, wmma::mem_col_major);
        }
}

// ============================================================
extern "C" void kernel_launch(void* const* d_in, const int* in_sizes, int n_in,
                              void* d_out, int out_size)
{
    const float* x      = (const float*)d_in[0];
    const float* sims   = (const float*)d_in[1];
    const float* w_qk   = (const float*)d_in[2];
    const float* b_qk   = (const float*)d_in[3];
    const float* w_v    = (const float*)d_in[4];
    const float* b_v    = (const float*)d_in[5];
    const float* w_proj = (const float*)d_in[6];
    const float* b_proj = (const float*)d_in[7];
    float* out = (float*)d_out;

    cudaFuncSetAttribute(k_qkv_wmma,  cudaFuncAttributeMaxDynamicSharedMemorySize, QKV_SMEM);
    cudaFuncSetAttribute(k_pwd,       cudaFuncAttributeMaxDynamicSharedMemorySize, PWD_SMEM);
    cudaFuncSetAttribute(k_attn,      cudaFuncAttributeMaxDynamicSharedMemorySize, ATT_SMEM);
    cudaFuncSetAttribute(k_proj_wmma, cudaFuncAttributeMaxDynamicSharedMemorySize, PRJ_SMEM);

    k_qkv_wmma <<<NPIX/128, 256, QKV_SMEM>>>(x, w_qk, b_qk, w_v, b_v);
    k_pwd      <<<dim3(WW/32, HH/16, BB),    dim3(32,16), PWD_SMEM>>>(sims);
    k_attn     <<<dim3(WW/32, HH/8, BB*NHH), dim3(32,8),  ATT_SMEM>>>();
    k_proj_wmma<<<NPIX/128, 256, PRJ_SMEM>>>(w_proj, b_proj, out);
}

// round 10
// speedup vs baseline: 2.6329x; 1.2788x over previous
#include <cuda_runtime.h>
#include <mma.h>
#include <cuda_fp16.h>
#include <math.h>

using namespace nvcuda;

#define BB 8
#define CC 128
#define HH 128
#define WW 128
#define NHH 4
#define HDD 32
#define SG2 256
#define HWP (HH*WW)      // 16384
#define NPIX (BB*HWP)    // 131072
#define KK2 25
#define SCALE 0.17677669529663687f   // 1/sqrt(32)

// ---- scratch (static device arrays; no runtime allocation) ----
static __device__ __align__(16) __half g_q[(size_t)NPIX*CC];
static __device__ __align__(16) __half g_k[(size_t)NPIX*CC];
static __device__ __align__(16) __half g_v[(size_t)NPIX*CC];
static __device__ __align__(16) __half g_agg[(size_t)NPIX*CC];
static __device__ __align__(16) __half g_pwd[(size_t)NPIX*KK2];  // x256 scale (cancels)

#define LDH 136                       // fp16 smem row stride (halfs)

__device__ __forceinline__ uint2 f4toh4(float4 v) {
    __half2 lo = __floats2half2_rn(v.x, v.y);
    __half2 hi = __floats2half2_rn(v.z, v.w);
    uint2 r;
    r.x = *(unsigned*)&lo;
    r.y = *(unsigned*)&hi;
    return r;
}

// ============================================================
// Kernel 1: QKV GEMM via WMMA fp16 (fp32 acc), fp16 outputs via
// fragment-level f32->f16 conversion. (R9-proven, unchanged.)
// ============================================================
#define QKV_SMEM (16*132*4 + 2*128*LDH*2)   // 78080 B -> 2 blocks/SM

__global__ void __launch_bounds__(256, 2)
k_qkv_wmma(const float* __restrict__ x, const float* __restrict__ w_qk,
           const float* __restrict__ b_qk, const float* __restrict__ w_v,
           const float* __restrict__ b_v)
{
    extern __shared__ char smraw[];
    float*  bias_s = (float*)smraw;                    // [16][132]
    __half* As     = (__half*)(smraw + 16*132*4);      // [k=128][m=128] ld LDH
    __half* Bs     = As + 128*LDH;                     // [k=128][n=128] ld LDH

    const int tid = threadIdx.x;
    const int wid = tid >> 5;
    const int wm  = wid & 3;
    const int wn  = wid >> 2;
    const int p0  = blockIdx.x * 128;
    const int b   = p0 / HWP;
    const int ij0 = p0 % HWP;
    const float* xb = x + (size_t)b*CC*HWP + ij0;

#pragma unroll
    for (int it = 0; it < 16; it++) {
        int idx = tid + it*256;
        int k = idx >> 5, m4 = idx & 31;
        *(uint2*)(As + k*LDH + m4*4) =
            f4toh4(*(const float4*)(xb + (size_t)k*HWP + m4*4));
    }

    for (int nt = 0; nt < 3; nt++) {
        __syncthreads();
#pragma unroll
        for (int it = 0; it < 16; it++) {
            int idx = tid + it*256;
            int k = idx >> 5, n4 = idx & 31;
            const float* src = (nt < 2) ? (w_qk + k*2*CC + nt*128 + n4*4)
                                        : (w_v  + k*CC  + n4*4);
            *(uint2*)(Bs + k*LDH + n4*4) = f4toh4(*(const float4*)src);
        }
        if (tid < 128) {
            float bv = (nt < 2) ? b_qk[nt*128 + tid] : b_v[tid];
#pragma unroll
            for (int r = 0; r < 16; r++) bias_s[r*132 + tid] = bv;
        }
        __syncthreads();

        wmma::fragment<wmma::accumulator, 16,16,16, float> acc[2][4];
#pragma unroll
        for (int mi = 0; mi < 2; mi++)
#pragma unroll
            for (int ni = 0; ni < 4; ni++)
                wmma::load_matrix_sync(acc[mi][ni], bias_s + wn*64 + ni*16,
                                       132, wmma::mem_row_major);

#pragma unroll
        for (int k0 = 0; k0 < CC; k0 += 16) {
            wmma::fragment<wmma::matrix_a, 16,16,16, __half, wmma::col_major> a[2];
#pragma unroll
            for (int mi = 0; mi < 2; mi++)
                wmma::load_matrix_sync(a[mi], As + k0*LDH + wm*32 + mi*16, LDH);
            wmma::fragment<wmma::matrix_b, 16,16,16, __half, wmma::row_major> bf[4];
#pragma unroll
            for (int ni = 0; ni < 4; ni++)
                wmma::load_matrix_sync(bf[ni], Bs + k0*LDH + wn*64 + ni*16, LDH);
#pragma unroll
            for (int mi = 0; mi < 2; mi++)
#pragma unroll
                for (int ni = 0; ni < 4; ni++)
                    wmma::mma_sync(acc[mi][ni], a[mi], bf[ni], acc[mi][ni]);
        }

        __half* dstbase = (nt == 0) ? g_q : (nt == 1) ? g_k : g_v;
#pragma unroll
        for (int mi = 0; mi < 2; mi++)
#pragma unroll
            for (int ni = 0; ni < 4; ni++) {
                wmma::fragment<wmma::accumulator, 16,16,16, __half> hacc;
#pragma unroll
                for (int e = 0; e < 8; e++)
                    hacc.x[e] = __float2half(acc[mi][ni].x[e]);
                int n0 = wn*64 + ni*16;
                int head = n0 >> 5, d0 = n0 & 31;
                __half* dst = dstbase +
                    ((size_t)(b*NHH + head)*HWP + ij0 + wm*32 + mi*16)*HDD + d0;
                wmma::store_matrix_sync(dst, hacc, HDD, wmma::mem_row_major);
            }
    }
}

// ============================================================
// Kernel 2: pwd via HFMA2. Per 32-chan chunk: two half2 accs,
// flushed to fp32 acc[25] per chunk (error ~4e-5).
// 16x32 tile, 512 threads, 57.6 KB smem -> 2 blocks/SM.
// ============================================================
#define PWD_SMEM (720*40*2)   // 57600 B

__global__ void __launch_bounds__(512, 2)
k_pwd(const float* __restrict__ sims)
{
    extern __shared__ __half Sh[];  // [720 halo pixels][40]
    const int b  = blockIdx.z;
    const int i0 = blockIdx.y * 16;
    const int j0 = blockIdx.x * 32;
    const int tx = threadIdx.x, ty = threadIdx.y;
    const int tid = ty*32 + tx;
    const float* sb = sims + (size_t)b*HWP*SG2;

    float acc[KK2];
#pragma unroll
    for (int k=0;k<KK2;k++) acc[k] = 0.f;

    for (int scc = 0; scc < SG2; scc += 32) {
        __syncthreads();
        for (int idx = tid; idx < 720*4; idx += 512) {
            int pix = idx >> 2, v = idx & 3;
            int hr = pix / 36, hc = pix - hr*36;
            int gi = i0 - 2 + hr, gj = j0 - 2 + hc;
            uint4 o = make_uint4(0,0,0,0);
            if ((unsigned)gi < HH && (unsigned)gj < WW) {
                const float* src = sb + ((size_t)gi*WW + gj)*SG2 + scc + v*8;
                float4 f0 = *(const float4*)src;
                float4 f1 = *(const float4*)(src + 4);
                f0.x*=16.f; f0.y*=16.f; f0.z*=16.f; f0.w*=16.f;
                f1.x*=16.f; f1.y*=16.f; f1.z*=16.f; f1.w*=16.f;
                uint2 h0 = f4toh4(f0), h1 = f4toh4(f1);
                o = make_uint4(h0.x, h0.y, h1.x, h1.y);
            }
            *(uint4*)(Sh + pix*40 + v*8) = o;
        }
        __syncthreads();

        __half2 own2[16];
        {
            const __half* op = Sh + ((ty+2)*36 + (tx+2))*40;
#pragma unroll
            for (int v=0; v<4; v++) {
                uint4 r = *(const uint4*)(op + v*8);
                own2[v*4+0] = *(__half2*)&r.x;
                own2[v*4+1] = *(__half2*)&r.y;
                own2[v*4+2] = *(__half2*)&r.z;
                own2[v*4+3] = *(__half2*)&r.w;
            }
        }
#pragma unroll
        for (int di=0; di<5; di++) {
#pragma unroll
            for (int dj=0; dj<5; dj++) {
                const __half* np = Sh + ((ty+di)*36 + (tx+dj))*40;
                __half2 a2 = __float2half2_rn(0.f);
                __half2 b2 = __float2half2_rn(0.f);
#pragma unroll
                for (int v=0; v<4; v++) {
                    uint4 r = *(const uint4*)(np + v*8);
                    a2 = __hfma2(own2[v*4+0], *(__half2*)&r.x, a2);
                    b2 = __hfma2(own2[v*4+1], *(__half2*)&r.y, b2);
                    a2 = __hfma2(own2[v*4+2], *(__half2*)&r.z, a2);
                    b2 = __hfma2(own2[v*4+3], *(__half2*)&r.w, b2);
                }
                float2 fa = __half22float2(a2);
                float2 fb = __half22float2(b2);
                acc[di*5+dj] += (fa.x + fa.y) + (fb.x + fb.y);
            }
        }
    }
    const size_t p = (size_t)b*HWP + (size_t)(i0+ty)*WW + (j0+tx);
#pragma unroll
    for (int k=0;k<KK2;k++) g_pwd[p*KK2 + k] = __float2half(acc[k]);
}

// ============================================================
// Kernel 3: attention + V agg via HFMA2.
// Scores: two half2 accs per neighbor, fp32 reduce.
// V-agg: half2 accs per di-row (5 adds), fp32 flush per row.
// ============================================================
#define ATT_SMEM (2*432*40*2)   // 69120 B -> 2 blocks/SM

__global__ void __launch_bounds__(256, 2)
k_attn()
{
    extern __shared__ __half sh[];
    __half* Kh = sh;              // [432][40]
    __half* Vh = sh + 432*40;

    const int bh = blockIdx.z;
    const int b  = bh >> 2;
    const int h  = bh & 3;
    const int i0 = blockIdx.y * 8;
    const int j0 = blockIdx.x * 32;
    const int tx = threadIdx.x, ty = threadIdx.y;
    const int tid = ty*32 + tx;
    const size_t headoff = (size_t)bh*HWP*HDD;
    const int ij = (i0+ty)*WW + (j0+tx);

    const __half* kb = g_k + headoff;
    const __half* vb = g_v + headoff;
    for (int idx = tid; idx < 432*4; idx += 256) {
        int pix = idx >> 2, v = idx & 3;
        int hr = pix / 36, hc = pix - hr*36;
        int gi = i0 - 2 + hr, gj = j0 - 2 + hc;
        uint4 kp = make_uint4(0,0,0,0), vp = make_uint4(0,0,0,0);
        if ((unsigned)gi < HH && (unsigned)gj < WW) {
            size_t off = (size_t)(gi*WW + gj)*HDD + v*8;
            kp = *(const uint4*)(kb + off);
            vp = *(const uint4*)(vb + off);
        }
        *(uint4*)(Kh + pix*40 + v*8) = kp;
        *(uint4*)(Vh + pix*40 + v*8) = vp;
    }

    __half2 q2[16];
    {
        const __half* qp = g_q + headoff + (size_t)ij*HDD;
#pragma unroll
        for (int v=0; v<4; v++) {
            uint4 r = *(const uint4*)(qp + v*8);
            q2[v*4+0] = *(__half2*)&r.x;
            q2[v*4+1] = *(__half2*)&r.y;
            q2[v*4+2] = *(__half2*)&r.z;
            q2[v*4+3] = *(__half2*)&r.w;
        }
    }
    __syncthreads();

    const __half* pw = g_pwd + ((size_t)b*HWP + ij)*KK2;
    float w[KK2]; float ssum = 0.f;
#pragma unroll
    for (int di=0; di<5; di++) {
#pragma unroll
        for (int dj=0; dj<5; dj++) {
            const __half* np = Kh + ((ty+di)*36 + (tx+dj))*40;
            __half2 a2 = __float2half2_rn(0.f);
            __half2 b2 = __float2half2_rn(0.f);
#pragma unroll
            for (int v=0; v<4; v++) {
                uint4 r = *(const uint4*)(np + v*8);
                a2 = __hfma2(q2[v*4+0], *(__half2*)&r.x, a2);
                b2 = __hfma2(q2[v*4+1], *(__half2*)&r.y, b2);
                a2 = __hfma2(q2[v*4+2], *(__half2*)&r.z, a2);
                b2 = __hfma2(q2[v*4+3], *(__half2*)&r.w, b2);
            }
            float2 fa = __half22float2(a2);
            float2 fb = __half22float2(b2);
            float s = (fa.x + fa.y) + (fb.x + fb.y);
            int kk = di*5+dj;
            w[kk] = __expf(s * SCALE) * __half2float(pw[kk]);
            ssum += w[kk];
        }
    }
    const float inv = 1.f / fmaxf(ssum, 1e-30f);

    float out[32];
#pragma unroll
    for (int v=0;v<32;v++) out[v] = 0.f;
#pragma unroll
    for (int di=0; di<5; di++) {
        __half2 o2[16];
#pragma unroll
        for (int j=0;j<16;j++) o2[j] = __float2half2_rn(0.f);
#pragma unroll
        for (int dj=0; dj<5; dj++) {
            __half2 wk2 = __float2half2_rn(w[di*5+dj] * inv);
            const __half* np = Vh + ((ty+di)*36 + (tx+dj))*40;
#pragma unroll
            for (int v=0; v<4; v++) {
                uint4 r = *(const uint4*)(np + v*8);
                o2[v*4+0] = __hfma2(wk2, *(__half2*)&r.x, o2[v*4+0]);
                o2[v*4+1] = __hfma2(wk2, *(__half2*)&r.y, o2[v*4+1]);
                o2[v*4+2] = __hfma2(wk2, *(__half2*)&r.z, o2[v*4+2]);
                o2[v*4+3] = __hfma2(wk2, *(__half2*)&r.w, o2[v*4+3]);
            }
        }
#pragma unroll
        for (int j=0;j<16;j++) {
            float2 f = __half22float2(o2[j]);
            out[2*j]   += f.x;
            out[2*j+1] += f.y;
        }
    }
    __half* ag = g_agg + ((size_t)b*HWP + ij)*CC + h*HDD;
#pragma unroll
    for (int v=0; v<4; v++) {
        uint2 h0 = f4toh4(make_float4(out[v*8+0], out[v*8+1], out[v*8+2], out[v*8+3]));
        uint2 h1 = f4toh4(make_float4(out[v*8+4], out[v*8+5], out[v*8+6], out[v*8+7]));
        *(uint4*)(ag + v*8) = make_uint4(h0.x, h0.y, h1.x, h1.y);
    }
}

// ============================================================
// Kernel 4: proj GEMM via WMMA fp16 + free BCHW transpose store.
// ============================================================
#define PRJ_SMEM (16*132*4 + 2*128*LDH*2)   // 78080 B -> 2 blocks/SM

__global__ void __launch_bounds__(256, 2)
k_proj_wmma(const float* __restrict__ w_proj, const float* __restrict__ b_proj,
            float* __restrict__ out)
{
    extern __shared__ char smraw[];
    float*  bias_s = (float*)smraw;                    // [16][132]
    __half* As     = (__half*)(smraw + 16*132*4);      // [m=128][k=128] ld LDH
    __half* Bs     = As + 128*LDH;                     // [k=128][n=128] ld LDH

    const int tid = threadIdx.x;
    const int wid = tid >> 5;
    const int wm  = wid & 3;
    const int wn  = wid >> 2;
    const int p0  = blockIdx.x * 128;
    const int b   = p0 / HWP;
    const int ij0 = p0 % HWP;

    const __half* ab = g_agg + (size_t)p0 * CC;
#pragma unroll
    for (int it = 0; it < 8; it++) {
        int idx = tid + it*256;
        int m = idx >> 4, k8 = idx & 15;
        *(uint4*)(As + m*LDH + k8*8) = *(const uint4*)(ab + (size_t)m*CC + k8*8);
    }
#pragma unroll
    for (int it = 0; it < 16; it++) {
        int idx = tid + it*256;
        int k = idx >> 5, n4 = idx & 31;
        *(uint2*)(Bs + k*LDH + n4*4) =
            f4toh4(*(const float4*)(w_proj + k*CC + n4*4));
    }
    if (tid < 128) {
        float bv = b_proj[tid];
#pragma unroll
        for (int r = 0; r < 16; r++) bias_s[r*132 + tid] = bv;
    }
    __syncthreads();

    wmma::fragment<wmma::accumulator, 16,16,16, float> acc[2][4];
#pragma unroll
    for (int mi = 0; mi < 2; mi++)
#pragma unroll
        for (int ni = 0; ni < 4; ni++)
            wmma::load_matrix_sync(acc[mi][ni], bias_s + wn*64 + ni*16,
                                   132, wmma::mem_row_major);

#pragma unroll
    for (int k0 = 0; k0 < CC; k0 += 16) {
        wmma::fragment<wmma::matrix_a, 16,16,16, __half, wmma::row_major> a[2];
#pragma unroll
        for (int mi = 0; mi < 2; mi++)
            wmma::load_matrix_sync(a[mi], As + (wm*32 + mi*16)*LDH + k0, LDH);
        wmma::fragment<wmma::matrix_b, 16,16,16, __half, wmma::row_major> bf[4];
#pragma unroll
        for (int ni = 0; ni < 4; ni++)
            wmma::load_matrix_sync(bf[ni], Bs + k0*LDH + wn*64 + ni*16, LDH);
#pragma unroll
        for (int mi = 0; mi < 2; mi++)
#pragma unroll
            for (int ni = 0; ni < 4; ni++)
                wmma::mma_sync(acc[mi][ni], a[mi], bf[ni], acc[mi][ni]);
    }

    float* ob = out + (size_t)b*CC*HWP + ij0;
#pragma unroll
    for (int mi = 0; mi < 2; mi++)
#pragma unroll
        for (int ni = 0; ni < 4; ni++) {
            int n0 = wn*64 + ni*16;
            int m0 = wm*32 + mi*16;
            wmma::store_matrix_sync(ob + (size_t)n0*HWP + m0, acc[mi][ni],
                                    HWP, wmma::mem_col_major);
        }
}

// ============================================================
extern "C" void kernel_launch(void* const* d_in, const int* in_sizes, int n_in,
                              void* d_out, int out_size)
{
    const float* x      = (const float*)d_in[0];
    const float* sims   = (const float*)d_in[1];
    const float* w_qk   = (const float*)d_in[2];
    const float* b_qk   = (const float*)d_in[3];
    const float* w_v    = (const float*)d_in[4];
    const float* b_v    = (const float*)d_in[5];
    const float* w_proj = (const float*)d_in[6];
    const float* b_proj = (const float*)d_in[7];
    float* out = (float*)d_out;

    cudaFuncSetAttribute(k_qkv_wmma,  cudaFuncAttributeMaxDynamicSharedMemorySize, QKV_SMEM);
    cudaFuncSetAttribute(k_pwd,       cudaFuncAttributeMaxDynamicSharedMemorySize, PWD_SMEM);
    cudaFuncSetAttribute(k_attn,      cudaFuncAttributeMaxDynamicSharedMemorySize, ATT_SMEM);
    cudaFuncSetAttribute(k_proj_wmma, cudaFuncAttributeMaxDynamicSharedMemorySize, PRJ_SMEM);

    k_qkv_wmma <<<NPIX/128, 256, QKV_SMEM>>>(x, w_qk, b_qk, w_v, b_v);
    k_pwd      <<<dim3(WW/32, HH/16, BB),    dim3(32,16), PWD_SMEM>>>(sims);
    k_attn     <<<dim3(WW/32, HH/8, BB*NHH), dim3(32,8),  ATT_SMEM>>>();
    k_proj_wmma<<<NPIX/128, 256, PRJ_SMEM>>>(w_proj, b_proj, out);
}

// round 12
// speedup vs baseline: 2.7092x; 1.0290x over previous
#include <cuda_runtime.h>
#include <mma.h>
#include <cuda_fp16.h>
#include <math.h>

using namespace nvcuda;

#define BB 8
#define CC 128
#define HH 128
#define WW 128
#define NHH 4
#define HDD 32
#define SG2 256
#define HWP (HH*WW)      // 16384
#define NPIX (BB*HWP)    // 131072
#define KK2 25
#define SCALE 0.17677669529663687f   // 1/sqrt(32)

// ---- scratch (static device arrays; no runtime allocation) ----
static __device__ __align__(16) __half g_q[(size_t)NPIX*CC];
static __device__ __align__(16) __half g_k[(size_t)NPIX*CC];
static __device__ __align__(16) __half g_v[(size_t)NPIX*CC];
static __device__ __align__(16) __half g_agg[(size_t)NPIX*CC];
static __device__ __align__(16) __half g_pwd[(size_t)NPIX*KK2];  // x256 scale (cancels)

#define LDH 136    // fp16 smem row stride for GEMMs (halfs)
#define SLD 40     // fp16 smem row stride for stencils (halfs) — 80 B = 5*16 ✓

__device__ __forceinline__ uint2 f4toh4(float4 v) {
    __half2 lo = __floats2half2_rn(v.x, v.y);
    __half2 hi = __floats2half2_rn(v.z, v.w);
    uint2 r;
    r.x = *(unsigned*)&lo;
    r.y = *(unsigned*)&hi;
    return r;
}

// 32-channel dot (q in permuted chunk order matching r0..r3), fp32 reduce.
__device__ __forceinline__ float dot32v(const __half2* q2,
        uint4 r0, uint4 r1, uint4 r2, uint4 r3)
{
    __half2 a2 = __float2half2_rn(0.f);
    __half2 b2 = __float2half2_rn(0.f);
    a2 = __hfma2(q2[0],  *(__half2*)&r0.x, a2);
    b2 = __hfma2(q2[1],  *(__half2*)&r0.y, b2);
    a2 = __hfma2(q2[2],  *(__half2*)&r0.z, a2);
    b2 = __hfma2(q2[3],  *(__half2*)&r0.w, b2);
    a2 = __hfma2(q2[4],  *(__half2*)&r1.x, a2);
    b2 = __hfma2(q2[5],  *(__half2*)&r1.y, b2);
    a2 = __hfma2(q2[6],  *(__half2*)&r1.z, a2);
    b2 = __hfma2(q2[7],  *(__half2*)&r1.w, b2);
    a2 = __hfma2(q2[8],  *(__half2*)&r2.x, a2);
    b2 = __hfma2(q2[9],  *(__half2*)&r2.y, b2);
    a2 = __hfma2(q2[10], *(__half2*)&r2.z, a2);
    b2 = __hfma2(q2[11], *(__half2*)&r2.w, b2);
    a2 = __hfma2(q2[12], *(__half2*)&r3.x, a2);
    b2 = __hfma2(q2[13], *(__half2*)&r3.y, b2);
    a2 = __hfma2(q2[14], *(__half2*)&r3.z, a2);
    b2 = __hfma2(q2[15], *(__half2*)&r3.w, b2);
    float2 fa = __half22float2(a2);
    float2 fb = __half22float2(b2);
    return (fa.x + fa.y) + (fb.x + fb.y);
}

__device__ __forceinline__ void fma16(__half2* o, __half2 wk2, uint4 r0, uint4 r1)
{
    o[0] = __hfma2(wk2, *(__half2*)&r0.x, o[0]);
    o[1] = __hfma2(wk2, *(__half2*)&r0.y, o[1]);
    o[2] = __hfma2(wk2, *(__half2*)&r0.z, o[2]);
    o[3] = __hfma2(wk2, *(__half2*)&r0.w, o[3]);
    o[4] = __hfma2(wk2, *(__half2*)&r1.x, o[4]);
    o[5] = __hfma2(wk2, *(__half2*)&r1.y, o[5]);
    o[6] = __hfma2(wk2, *(__half2*)&r1.z, o[6]);
    o[7] = __hfma2(wk2, *(__half2*)&r1.w, o[7]);
}

// ============================================================
// Kernel 1: QKV GEMM via WMMA fp16 (fp32 acc). (R10-proven, unchanged.)
// ============================================================
#define QKV_SMEM (16*132*4 + 2*128*LDH*2)   // 78080 B -> 2 blocks/SM

__global__ void __launch_bounds__(256, 2)
k_qkv_wmma(const float* __restrict__ x, const float* __restrict__ w_qk,
           const float* __restrict__ b_qk, const float* __restrict__ w_v,
           const float* __restrict__ b_v)
{
    extern __shared__ char smraw[];
    float*  bias_s = (float*)smraw;                    // [16][132]
    __half* As     = (__half*)(smraw + 16*132*4);      // [k=128][m=128] ld LDH
    __half* Bs     = As + 128*LDH;                     // [k=128][n=128] ld LDH

    const int tid = threadIdx.x;
    const int wid = tid >> 5;
    const int wm  = wid & 3;
    const int wn  = wid >> 2;
    const int p0  = blockIdx.x * 128;
    const int b   = p0 / HWP;
    const int ij0 = p0 % HWP;
    const float* xb = x + (size_t)b*CC*HWP + ij0;

#pragma unroll
    for (int it = 0; it < 16; it++) {
        int idx = tid + it*256;
        int k = idx >> 5, m4 = idx & 31;
        *(uint2*)(As + k*LDH + m4*4) =
            f4toh4(*(const float4*)(xb + (size_t)k*HWP + m4*4));
    }

    for (int nt = 0; nt < 3; nt++) {
        __syncthreads();
#pragma unroll
        for (int it = 0; it < 16; it++) {
            int idx = tid + it*256;
            int k = idx >> 5, n4 = idx & 31;
            const float* src = (nt < 2) ? (w_qk + k*2*CC + nt*128 + n4*4)
                                        : (w_v  + k*CC  + n4*4);
            *(uint2*)(Bs + k*LDH + n4*4) = f4toh4(*(const float4*)src);
        }
        if (tid < 128) {
            float bv = (nt < 2) ? b_qk[nt*128 + tid] : b_v[tid];
#pragma unroll
            for (int r = 0; r < 16; r++) bias_s[r*132 + tid] = bv;
        }
        __syncthreads();

        wmma::fragment<wmma::accumulator, 16,16,16, float> acc[2][4];
#pragma unroll
        for (int mi = 0; mi < 2; mi++)
#pragma unroll
            for (int ni = 0; ni < 4; ni++)
                wmma::load_matrix_sync(acc[mi][ni], bias_s + wn*64 + ni*16,
                                       132, wmma::mem_row_major);

#pragma unroll
        for (int k0 = 0; k0 < CC; k0 += 16) {
            wmma::fragment<wmma::matrix_a, 16,16,16, __half, wmma::col_major> a[2];
#pragma unroll
            for (int mi = 0; mi < 2; mi++)
                wmma::load_matrix_sync(a[mi], As + k0*LDH + wm*32 + mi*16, LDH);
            wmma::fragment<wmma::matrix_b, 16,16,16, __half, wmma::row_major> bf[4];
#pragma unroll
            for (int ni = 0; ni < 4; ni++)
                wmma::load_matrix_sync(bf[ni], Bs + k0*LDH + wn*64 + ni*16, LDH);
#pragma unroll
            for (int mi = 0; mi < 2; mi++)
#pragma unroll
                for (int ni = 0; ni < 4; ni++)
                    wmma::mma_sync(acc[mi][ni], a[mi], bf[ni], acc[mi][ni]);
        }

        __half* dstbase = (nt == 0) ? g_q : (nt == 1) ? g_k : g_v;
#pragma unroll
        for (int mi = 0; mi < 2; mi++)
#pragma unroll
            for (int ni = 0; ni < 4; ni++) {
                wmma::fragment<wmma::accumulator, 16,16,16, __half> hacc;
#pragma unroll
                for (int e = 0; e < 8; e++)
                    hacc.x[e] = __float2half(acc[mi][ni].x[e]);
                int n0 = wn*64 + ni*16;
                int head = n0 >> 5, d0 = n0 & 31;
                __half* dst = dstbase +
                    ((size_t)(b*NHH + head)*HWP + ij0 + wm*32 + mi*16)*HDD + d0;
                wmma::store_matrix_sync(dst, hacc, HDD, wmma::mem_row_major);
            }
    }
}

// ============================================================
// Kernel 2: pwd, pixel-paired + XOR chunk rotation (conflict-free).
// 8x32 tile, 128 threads; each thread does pixels (2tx, 2tx+1).
// ============================================================
#define PWD_SMEM (432*SLD*2)   // 34560 B

__global__ void __launch_bounds__(128, 4)
k_pwd(const float* __restrict__ sims)
{
    extern __shared__ __half Sh[];  // [432][40]
    const int b  = blockIdx.z;
    const int i0 = blockIdx.y * 8;
    const int j0 = blockIdx.x * 32;
    const int tx = threadIdx.x;     // 0..15
    const int ty = threadIdx.y;     // 0..7
    const int tid = ty*16 + tx;
    const int rot = (tx >> 2) & 1;
    const float* sb = sims + (size_t)b*HWP*SG2;

    float acc0[KK2], acc1[KK2];
#pragma unroll
    for (int k=0;k<KK2;k++) { acc0[k]=0.f; acc1[k]=0.f; }

    for (int scc = 0; scc < SG2; scc += 32) {
        __syncthreads();
        for (int idx = tid; idx < 432*4; idx += 128) {
            int pix = idx >> 2, v = idx & 3;
            int hr = pix / 36, hc = pix - hr*36;
            int gi = i0 - 2 + hr, gj = j0 - 2 + hc;
            uint4 o = make_uint4(0,0,0,0);
            if ((unsigned)gi < HH && (unsigned)gj < WW) {
                const float* src = sb + ((size_t)gi*WW + gj)*SG2 + scc + v*8;
                float4 f0 = *(const float4*)src;
                float4 f1 = *(const float4*)(src + 4);
                f0.x*=16.f; f0.y*=16.f; f0.z*=16.f; f0.w*=16.f;
                f1.x*=16.f; f1.y*=16.f; f1.z*=16.f; f1.w*=16.f;
                uint2 h0 = f4toh4(f0), h1 = f4toh4(f1);
                o = make_uint4(h0.x, h0.y, h1.x, h1.y);
            }
            *(uint4*)(Sh + pix*SLD + v*8) = o;
        }
        __syncthreads();

        // own vectors, loaded in permuted chunk order (chunk i^rot at slot i)
        __half2 oa[16], ob[16];
        {
            const __half* p0 = Sh + ((ty+2)*36 + (2*tx+2))*SLD;
#pragma unroll
            for (int v=0; v<4; v++) {
                uint4 r = *(const uint4*)(p0 + ((v^rot)<<3));
                oa[v*4+0]=*(__half2*)&r.x; oa[v*4+1]=*(__half2*)&r.y;
                oa[v*4+2]=*(__half2*)&r.z; oa[v*4+3]=*(__half2*)&r.w;
                uint4 s = *(const uint4*)(p0 + SLD + ((v^rot)<<3));
                ob[v*4+0]=*(__half2*)&s.x; ob[v*4+1]=*(__half2*)&s.y;
                ob[v*4+2]=*(__half2*)&s.z; ob[v*4+3]=*(__half2*)&s.w;
            }
        }
#pragma unroll
        for (int di=0; di<5; di++) {
#pragma unroll
            for (int djc=0; djc<6; djc++) {
                const __half* np = Sh + ((ty+di)*36 + (2*tx+djc))*SLD;
                uint4 r0 = *(const uint4*)(np + ((0^rot)<<3));
                uint4 r1 = *(const uint4*)(np + ((1^rot)<<3));
                uint4 r2 = *(const uint4*)(np + ((2^rot)<<3));
                uint4 r3 = *(const uint4*)(np + ((3^rot)<<3));
                if (djc < 5) acc0[di*5+djc]   += dot32v(oa, r0,r1,r2,r3);
                if (djc > 0) acc1[di*5+djc-1] += dot32v(ob, r0,r1,r2,r3);
            }
        }
    }
    const size_t p = (size_t)b*HWP + (size_t)(i0+ty)*WW + (j0+2*tx);
#pragma unroll
    for (int k=0;k<KK2;k++) {
        g_pwd[p*KK2 + k]     = __float2half(acc0[k]);
        g_pwd[(p+1)*KK2 + k] = __float2half(acc1[k]);
    }
}

// ============================================================
// Kernel 3: attention + V agg, pixel-paired + XOR chunk rotation,
// single K->V smem buffer, weights packed half2 early (reg diet).
// ============================================================
#define ATT_SMEM (432*SLD*2)   // 34560 B

__global__ void __launch_bounds__(128, 4)
k_attn()
{
    extern __shared__ __half Hs[];  // [432][40]: K then V
    const int bh = blockIdx.z;
    const int b  = bh >> 2;
    const int h  = bh & 3;
    const int i0 = blockIdx.y * 8;
    const int j0 = blockIdx.x * 32;
    const int tx = threadIdx.x;     // 0..15
    const int ty = threadIdx.y;     // 0..7
    const int tid = ty*16 + tx;
    const int rot = (tx >> 2) & 1;
    const size_t headoff = (size_t)bh*HWP*HDD;
    const int ij0 = (i0+ty)*WW + (j0 + 2*tx);

    // ---- stage K ----
    const __half* kb = g_k + headoff;
    for (int idx = tid; idx < 432*4; idx += 128) {
        int pix = idx >> 2, v = idx & 3;
        int hr = pix / 36, hc = pix - hr*36;
        int gi = i0 - 2 + hr, gj = j0 - 2 + hc;
        uint4 kp = make_uint4(0,0,0,0);
        if ((unsigned)gi < HH && (unsigned)gj < WW)
            kp = *(const uint4*)(kb + (size_t)(gi*WW + gj)*HDD + v*8);
        *(uint4*)(Hs + pix*SLD + v*8) = kp;
    }

    // q pair, loaded from global in permuted chunk order
    __half2 qa[16], qb[16];
    {
        const __half* qp = g_q + headoff + (size_t)ij0*HDD;
#pragma unroll
        for (int v=0; v<4; v++) {
            uint4 r = *(const uint4*)(qp + ((v^rot)<<3));
            qa[v*4+0]=*(__half2*)&r.x; qa[v*4+1]=*(__half2*)&r.y;
            qa[v*4+2]=*(__half2*)&r.z; qa[v*4+3]=*(__half2*)&r.w;
            uint4 s = *(const uint4*)(qp + HDD + ((v^rot)<<3));
            qb[v*4+0]=*(__half2*)&s.x; qb[v*4+1]=*(__half2*)&s.y;
            qb[v*4+2]=*(__half2*)&s.z; qb[v*4+3]=*(__half2*)&s.w;
        }
    }
    __syncthreads();

    // ---- scores for the pair; weights packed half2 immediately ----
    const __half* pwp = g_pwd + ((size_t)b*HWP + ij0)*KK2;
    __half2 wh2[KK2];
    float ssum0 = 0.f, ssum1 = 0.f;
#pragma unroll
    for (int di=0; di<5; di++) {
#pragma unroll
        for (int djc=0; djc<6; djc++) {
            const __half* np = Hs + ((ty+di)*36 + (2*tx+djc))*SLD;
            uint4 r0 = *(const uint4*)(np + ((0^rot)<<3));
            uint4 r1 = *(const uint4*)(np + ((1^rot)<<3));
            uint4 r2 = *(const uint4*)(np + ((2^rot)<<3));
            uint4 r3 = *(const uint4*)(np + ((3^rot)<<3));
            if (djc < 5) {
                int kk = di*5+djc;
                float s = dot32v(qa, r0,r1,r2,r3);
                float w0 = __expf(s * SCALE) * __half2float(pwp[kk]);
                ssum0 += w0;
                wh2[kk] = __floats2half2_rn(w0, __low2float(wh2[kk]) * 0.f);
                // store w0 in low half; high half set below (djc>0 path)
                wh2[kk] = __halves2half2(__float2half(w0), __high2half(wh2[kk]));
            }
            if (djc > 0) {
                int kk = di*5+djc-1;
                float s = dot32v(qb, r0,r1,r2,r3);
                float w1 = __expf(s * SCALE) * __half2float(pwp[KK2+kk]);
                ssum1 += w1;
                wh2[kk] = __halves2half2(__low2half(wh2[kk]), __float2half(w1));
            }
        }
    }
    {
        __half2 inv2 = __floats2half2_rn(1.f / fmaxf(ssum0, 1e-30f),
                                         1.f / fmaxf(ssum1, 1e-30f));
#pragma unroll
        for (int k=0;k<KK2;k++) wh2[k] = __hmul2(wh2[k], inv2);
    }

    __syncthreads();   // done reading K

    // ---- stage V (reuse buffer) ----
    const __half* vb = g_v + headoff;
    for (int idx = tid; idx < 432*4; idx += 128) {
        int pix = idx >> 2, v = idx & 3;
        int hr = pix / 36, hc = pix - hr*36;
        int gi = i0 - 2 + hr, gj = j0 - 2 + hc;
        uint4 vp = make_uint4(0,0,0,0);
        if ((unsigned)gi < HH && (unsigned)gj < WW)
            vp = *(const uint4*)(vb + (size_t)(gi*WW + gj)*HDD + v*8);
        *(uint4*)(Hs + pix*SLD + v*8) = vp;
    }
    __syncthreads();

    // ---- V aggregation: two channel-halves, chunk-rotated loads ----
    __half* ag = g_agg + ((size_t)b*HWP + ij0)*CC + h*HDD;
#pragma unroll
    for (int ch = 0; ch < 2; ch++) {
        float out0[16], out1[16];
#pragma unroll
        for (int j=0;j<16;j++) { out0[j]=0.f; out1[j]=0.f; }
#pragma unroll
        for (int di=0; di<5; di++) {
            __half2 oa[8], ob[8];
#pragma unroll
            for (int j=0;j<8;j++) { oa[j]=__float2half2_rn(0.f); ob[j]=__float2half2_rn(0.f); }
#pragma unroll
            for (int djc=0; djc<6; djc++) {
                const __half* np = Hs + ((ty+di)*36 + (2*tx+djc))*SLD + ch*16;
                uint4 r0 = *(const uint4*)(np + ((0^rot)<<3));
                uint4 r1 = *(const uint4*)(np + ((1^rot)<<3));
                if (djc < 5) fma16(oa, __low2half2 (wh2[di*5+djc]),   r0, r1);
                if (djc > 0) fma16(ob, __high2half2(wh2[di*5+djc-1]), r0, r1);
            }
#pragma unroll
            for (int j=0;j<8;j++) {
                float2 fa = __half22float2(oa[j]);
                float2 fb = __half22float2(ob[j]);
                out0[2*j] += fa.x; out0[2*j+1] += fa.y;
                out1[2*j] += fb.x; out1[2*j+1] += fb.y;
            }
        }
        // accumulators are in loaded (permuted) order: slot v holds chunk v^rot
#pragma unroll
        for (int v=0; v<2; v++) {
            uint2 h0 = f4toh4(make_float4(out0[v*8+0],out0[v*8+1],out0[v*8+2],out0[v*8+3]));
            uint2 h1 = f4toh4(make_float4(out0[v*8+4],out0[v*8+5],out0[v*8+6],out0[v*8+7]));
            *(uint4*)(ag + ch*16 + ((v^rot)<<3)) = make_uint4(h0.x,h0.y,h1.x,h1.y);
            uint2 g0 = f4toh4(make_float4(out1[v*8+0],out1[v*8+1],out1[v*8+2],out1[v*8+3]));
            uint2 g1 = f4toh4(make_float4(out1[v*8+4],out1[v*8+5],out1[v*8+6],out1[v*8+7]));
            *(uint4*)(ag + CC + ch*16 + ((v^rot)<<3)) = make_uint4(g0.x,g0.y,g1.x,g1.y);
        }
    }
}

// ============================================================
// Kernel 4: proj GEMM via WMMA fp16 + free BCHW transpose store.
// (R10-proven, unchanged.)
// ============================================================
#define PRJ_SMEM (16*132*4 + 2*128*LDH*2)   // 78080 B -> 2 blocks/SM

__global__ void __launch_bounds__(256, 2)
k_proj_wmma(const float* __restrict__ w_proj, const float* __restrict__ b_proj,
            float* __restrict__ out)
{
    extern __shared__ char smraw[];
    float*  bias_s = (float*)smraw;                    // [16][132]
    __half* As     = (__half*)(smraw + 16*132*4);      // [m=128][k=128] ld LDH
    __half* Bs     = As + 128*LDH;                     // [k=128][n=128] ld LDH

    const int tid = threadIdx.x;
    const int wid = tid >> 5;
    const int wm  = wid & 3;
    const int wn  = wid >> 2;
    const int p0  = blockIdx.x * 128;
    const int b   = p0 / HWP;
    const int ij0 = p0 % HWP;

    const __half* ab = g_agg + (size_t)p0 * CC;
#pragma unroll
    for (int it = 0; it < 8; it++) {
        int idx = tid + it*256;
        int m = idx >> 4, k8 = idx & 15;
        *(uint4*)(As + m*LDH + k8*8) = *(const uint4*)(ab + (size_t)m*CC + k8*8);
    }
#pragma unroll
    for (int it = 0; it < 16; it++) {
        int idx = tid + it*256;
        int k = idx >> 5, n4 = idx & 31;
        *(uint2*)(Bs + k*LDH + n4*4) =
            f4toh4(*(const float4*)(w_proj + k*CC + n4*4));
    }
    if (tid < 128) {
        float bv = b_proj[tid];
#pragma unroll
        for (int r = 0; r < 16; r++) bias_s[r*132 + tid] = bv;
    }
    __syncthreads();

    wmma::fragment<wmma::accumulator, 16,16,16, float> acc[2][4];
#pragma unroll
    for (int mi = 0; mi < 2; mi++)
#pragma unroll
        for (int ni = 0; ni < 4; ni++)
            wmma::load_matrix_sync(acc[mi][ni], bias_s + wn*64 + ni*16,
                                   132, wmma::mem_row_major);

#pragma unroll
    for (int k0 = 0; k0 < CC; k0 += 16) {
        wmma::fragment<wmma::matrix_a, 16,16,16, __half, wmma::row_major> a[2];
#pragma unroll
        for (int mi = 0; mi < 2; mi++)
            wmma::load_matrix_sync(a[mi], As + (wm*32 + mi*16)*LDH + k0, LDH);
        wmma::fragment<wmma::matrix_b, 16,16,16, __half, wmma::row_major> bf[4];
#pragma unroll
        for (int ni = 0; ni < 4; ni++)
            wmma::load_matrix_sync(bf[ni], Bs + k0*LDH + wn*64 + ni*16, LDH);
#pragma unroll
        for (int mi = 0; mi < 2; mi++)
#pragma unroll
            for (int ni = 0; ni < 4; ni++)
                wmma::mma_sync(acc[mi][ni], a[mi], bf[ni], acc[mi][ni]);
    }

    float* ob = out + (size_t)b*CC*HWP + ij0;
#pragma unroll
    for (int mi = 0; mi < 2; mi++)
#pragma unroll
        for (int ni = 0; ni < 4; ni++) {
            int n0 = wn*64 + ni*16;
            int m0 = wm*32 + mi*16;
            wmma::store_matrix_sync(ob + (size_t)n0*HWP + m0, acc[mi][ni],
                                    HWP, wmma::mem_col_major);
        }
}

// ============================================================
extern "C" void kernel_launch(void* const* d_in, const int* in_sizes, int n_in,
                              void* d_out, int out_size)
{
    const float* x      = (const float*)d_in[0];
    const float* sims   = (const float*)d_in[1];
    const float* w_qk   = (const float*)d_in[2];
    const float* b_qk   = (const float*)d_in[3];
    const float* w_v    = (const float*)d_in[4];
    const float* b_v    = (const float*)d_in[5];
    const float* w_proj = (const float*)d_in[6];
    const float* b_proj = (const float*)d_in[7];
    float* out = (float*)d_out;

    cudaFuncSetAttribute(k_qkv_wmma,  cudaFuncAttributeMaxDynamicSharedMemorySize, QKV_SMEM);
    cudaFuncSetAttribute(k_pwd,       cudaFuncAttributeMaxDynamicSharedMemorySize, PWD_SMEM);
    cudaFuncSetAttribute(k_attn,      cudaFuncAttributeMaxDynamicSharedMemorySize, ATT_SMEM);
    cudaFuncSetAttribute(k_proj_wmma, cudaFuncAttributeMaxDynamicSharedMemorySize, PRJ_SMEM);

    k_qkv_wmma <<<NPIX/128, 256, QKV_SMEM>>>(x, w_qk, b_qk, w_v, b_v);
    k_pwd      <<<dim3(WW/32, HH/8, BB),      dim3(16,8), PWD_SMEM>>>(sims);
    k_attn     <<<dim3(WW/32, HH/8, BB*NHH),  dim3(16,8), ATT_SMEM>>>();
    k_proj_wmma<<<NPIX/128, 256, PRJ_SMEM>>>(w_proj, b_proj, out);
}